// round 1
// baseline (speedup 1.0000x reference)
#include <cuda_runtime.h>

#define BATCH 4
#define DIMC 96
#define HEADS 3
#define NBH 12            // BATCH*HEADS
#define WSQ 49
#define TPAD 56
#define QK_SCALE 0.17677669529663687f   // 32^-0.5

// ---------------- scratch (device globals; no allocation allowed) ----------
__device__ float g_qk [(size_t)NBH * 64 * 128 * 128];   // [bh][64: q*s | k][y][x]
__device__ float g_v  [(size_t)NBH * 32 * 128 * 128];   // [bh][32][y][x]
__device__ float g_att[(size_t)BATCH * DIMC * 128 * 128];
__device__ float g_w2 [64 * WSQ * TPAD];                // [c][s][t(pad 56)]

// ---------------- K0: repack attn_w [t][c][s] -> [c][s][t] (t padded) ------
__global__ void k0_prep(const float* __restrict__ attn_w) {
    int idx = blockIdx.x * 256 + threadIdx.x;
    if (idx >= 64 * WSQ * TPAD) return;
    int c = idx / (WSQ * TPAD);
    int r = idx - c * (WSQ * TPAD);
    int s = r / TPAD;
    int t = r - s * TPAD;
    g_w2[idx] = (t < WSQ) ? attn_w[(t * 64 + c) * WSQ + s] : 0.0f;
}

// ---------------- K1: 1x1 qkv conv, write qk (q pre-scaled) and v ----------
// block = one image row (128 px), loops 3 chunks of 96 oc (q,k,v)
__global__ __launch_bounds__(256, 2) void k1_qkv(const float* __restrict__ x,
                                                 const float* __restrict__ w,
                                                 const float* __restrict__ bias) {
    extern __shared__ float smem[];
    float* x_sh = smem;             // [96][128]
    float* w_sh = smem + 96 * 128;  // [96][96]
    const int tid = threadIdx.x;
    const int row = blockIdx.x;
    const int b   = blockIdx.y;
    const int m = tid & 31;   // pixel group: px = m*4 .. m*4+3
    const int n = tid >> 5;   // oc group:   oc96 = n*12 .. n*12+11

    const float* xb = x + (((size_t)b * DIMC) << 14) + (row << 7);
    for (int idx = tid; idx < 96 * 128; idx += 256) {
        int c = idx >> 7, px = idx & 127;
        x_sh[idx] = xb[(((size_t)c) << 14) + px];
    }

    for (int chunk = 0; chunk < 3; ++chunk) {   // chunk 0=q 1=k 2=v
        __syncthreads();
        const float* wsrc = w + chunk * 96 * 96;
        for (int idx = tid; idx < 96 * 96; idx += 256) w_sh[idx] = wsrc[idx];
        __syncthreads();

        float acc[4][12];
        #pragma unroll
        for (int i = 0; i < 4; ++i)
            #pragma unroll
            for (int u = 0; u < 12; ++u) acc[i][u] = 0.0f;

        for (int k = 0; k < 96; ++k) {
            float4 a4 = *(const float4*)&x_sh[(k << 7) + m * 4];
            #pragma unroll
            for (int u = 0; u < 12; ++u) {
                float bw = w_sh[(n * 12 + u) * 96 + k];   // warp-uniform broadcast
                acc[0][u] = fmaf(a4.x, bw, acc[0][u]);
                acc[1][u] = fmaf(a4.y, bw, acc[1][u]);
                acc[2][u] = fmaf(a4.z, bw, acc[2][u]);
                acc[3][u] = fmaf(a4.w, bw, acc[3][u]);
            }
        }

        #pragma unroll
        for (int u = 0; u < 12; ++u) {
            int oc96 = n * 12 + u;
            int head = oc96 >> 5, ch = oc96 & 31;
            int bh = b * HEADS + head;
            float bs = bias[chunk * 96 + oc96];
            float4 v4;
            v4.x = acc[0][u] + bs; v4.y = acc[1][u] + bs;
            v4.z = acc[2][u] + bs; v4.w = acc[3][u] + bs;
            float* dst;
            if (chunk == 0) {
                v4.x *= QK_SCALE; v4.y *= QK_SCALE; v4.z *= QK_SCALE; v4.w *= QK_SCALE;
                dst = g_qk + ((((size_t)bh * 64) + ch) << 14) + (row << 7) + m * 4;
            } else if (chunk == 1) {
                dst = g_qk + ((((size_t)bh * 64) + 32 + ch) << 14) + (row << 7) + m * 4;
            } else {
                dst = g_v + ((((size_t)bh * 32) + ch) << 14) + (row << 7) + m * 4;
            }
            *(float4*)dst = v4;
        }
    }
}

// ---------------- K2: logits conv (implicit GEMM) + softmax + attn.V -------
// block: 1 bh, 8x32 pixel tile, 256 threads.
// GEMM: M=256 px, N=56 (49 real t), K=64c*49s.
// thread = (g pixel-group of 8 px, n t-group of 7 t); tid = g*8 + n
//   -> warp has 4 g values x 8 n values: A reads broadcast, B reads 8 banks.
#define QKSH_ROW 39           // 38 halo cols + 1 pad (conflict-free A reads)
#define QKSH_C   546          // 14*39
#define HALO_N   532          // 14*38

__global__ __launch_bounds__(256, 2) void k2_attn(const float* __restrict__ attn_b) {
    extern __shared__ float smem[];
    float* qk_sh     = smem;                  // phase A: [8][14][39] = 4368
    float* B_sh      = smem + 8 * QKSH_C;     // phase A: [49][56]    = 2744
    float* logits_sh = smem;                  // phase B: [256][50]   = 12800
    float* v_sh      = smem + 256 * 50;       // phase B: [14][40][8] = 4480

    const int tid = threadIdx.x;
    const int bh  = blockIdx.z;
    const int ty0 = blockIdx.y * 8;
    const int tx0 = blockIdx.x * 32;
    const int n   = tid & 7;          // t-group: t = n*7 .. n*7+6
    const int g   = tid >> 3;         // pixel group
    const int gy  = g >> 2;           // tile y (0..7)
    const int gx0 = (g & 3) * 8;      // tile x base (0,8,16,24)

    float acc[8][7];
    #pragma unroll
    for (int j = 0; j < 8; ++j)
        #pragma unroll
        for (int tt = 0; tt < 7; ++tt) acc[j][tt] = 0.0f;

    for (int cblk = 0; cblk < 8; ++cblk) {
        __syncthreads();
        // load qk halo for 8 channels (zero-padded borders)
        for (int idx = tid; idx < 8 * HALO_N; idx += 256) {
            int cc = idx / HALO_N;
            int r  = idx - cc * HALO_N;
            int hy = r / 38, hx = r - hy * 38;
            int gyy = ty0 - 3 + hy, gxx = tx0 - 3 + hx;
            float val = 0.0f;
            if ((unsigned)gyy < 128u && (unsigned)gxx < 128u)
                val = g_qk[((((size_t)bh * 64) + cblk * 8 + cc) << 14) + (gyy << 7) + gxx];
            qk_sh[cc * QKSH_C + hy * QKSH_ROW + hx] = val;
        }
        for (int c = 0; c < 8; ++c) {
            __syncthreads();
            const float* wsrc = g_w2 + (cblk * 8 + c) * (WSQ * TPAD);
            for (int idx = tid; idx < WSQ * TPAD; idx += 256) B_sh[idx] = wsrc[idx];
            __syncthreads();
            const float* abase = qk_sh + c * QKSH_C + gy * QKSH_ROW + gx0;
            #pragma unroll 1
            for (int dy = 0; dy < 7; ++dy) {
                float av[14];                      // A row cached: reused across dx
                const float* arow = abase + dy * QKSH_ROW;
                #pragma unroll
                for (int i = 0; i < 14; ++i) av[i] = arow[i];
                #pragma unroll
                for (int dx = 0; dx < 7; ++dx) {
                    const float* brow = B_sh + (dy * 7 + dx) * TPAD + n * 7;
                    float bv[7];
                    #pragma unroll
                    for (int tt = 0; tt < 7; ++tt) bv[tt] = brow[tt];
                    #pragma unroll
                    for (int j = 0; j < 8; ++j)
                        #pragma unroll
                        for (int tt = 0; tt < 7; ++tt)
                            acc[j][tt] = fmaf(av[dx + j], bv[tt], acc[j][tt]);
                }
            }
        }
    }

    // per-thread bias values for its t range
    float bb[7];
    #pragma unroll
    for (int tt = 0; tt < 7; ++tt) {
        int t = n * 7 + tt;
        bb[tt] = (t < WSQ) ? attn_b[t] : 0.0f;
    }

    __syncthreads();   // compute done -> reuse smem for logits
    #pragma unroll
    for (int j = 0; j < 8; ++j) {
        int p = (gy << 5) + gx0 + j;
        #pragma unroll
        for (int tt = 0; tt < 7; ++tt) {
            int t = n * 7 + tt;
            if (t < WSQ) logits_sh[p * 50 + t] = acc[j][tt] + bb[tt];
        }
    }
    __syncthreads();

    // per-pixel softmax: thread tid owns pixel tid
    const int py = tid >> 5, px = tid & 31;
    float lg[WSQ];
    float mx = -1e30f;
    #pragma unroll
    for (int t = 0; t < WSQ; ++t) { lg[t] = logits_sh[tid * 50 + t]; mx = fmaxf(mx, lg[t]); }
    float sum = 0.0f;
    #pragma unroll
    for (int t = 0; t < WSQ; ++t) { lg[t] = __expf(lg[t] - mx); sum += lg[t]; }
    float inv = 1.0f / sum;
    #pragma unroll
    for (int t = 0; t < WSQ; ++t) lg[t] *= inv;

    const int b    = bh / HEADS;
    const int head = bh - b * HEADS;

    // attn . V  (v halo in chunks of 8 channels, channel-fastest smem for vec4 reads)
    for (int vcblk = 0; vcblk < 4; ++vcblk) {
        __syncthreads();
        for (int idx = tid; idx < 8 * HALO_N; idx += 256) {
            int cc = idx / HALO_N;
            int r  = idx - cc * HALO_N;
            int hy = r / 38, hx = r - hy * 38;
            int gyy = ty0 - 3 + hy, gxx = tx0 - 3 + hx;
            float val = 0.0f;
            if ((unsigned)gyy < 128u && (unsigned)gxx < 128u)
                val = g_v[((((size_t)bh * 32) + vcblk * 8 + cc) << 14) + (gyy << 7) + gxx];
            v_sh[(hy * 40 + hx) * 8 + cc] = val;
        }
        __syncthreads();

        float o[8];
        #pragma unroll
        for (int vc = 0; vc < 8; ++vc) o[vc] = 0.0f;
        #pragma unroll
        for (int dy = 0; dy < 7; ++dy) {
            #pragma unroll
            for (int dx = 0; dx < 7; ++dx) {
                float a = lg[dy * 7 + dx];
                const float4* vp = (const float4*)&v_sh[((py + dy) * 40 + px + dx) * 8];
                float4 v0 = vp[0], v1 = vp[1];
                o[0] = fmaf(a, v0.x, o[0]); o[1] = fmaf(a, v0.y, o[1]);
                o[2] = fmaf(a, v0.z, o[2]); o[3] = fmaf(a, v0.w, o[3]);
                o[4] = fmaf(a, v1.x, o[4]); o[5] = fmaf(a, v1.y, o[5]);
                o[6] = fmaf(a, v1.z, o[6]); o[7] = fmaf(a, v1.w, o[7]);
            }
        }
        #pragma unroll
        for (int vc = 0; vc < 8; ++vc)
            g_att[((((size_t)b * DIMC) + head * 32 + vcblk * 8 + vc) << 14)
                  + ((ty0 + py) << 7) + (tx0 + px)] = o[vc];
    }
}

// ---------------- K3: 1x1 proj -> d_out ------------------------------------
__global__ __launch_bounds__(256, 2) void k3_proj(const float* __restrict__ w,
                                                  const float* __restrict__ bias,
                                                  float* __restrict__ out) {
    extern __shared__ float smem[];
    float* x_sh = smem;             // [96][128]
    float* w_sh = smem + 96 * 128;  // [96][96]
    const int tid = threadIdx.x;
    const int row = blockIdx.x;
    const int b   = blockIdx.y;
    const int m = tid & 31;
    const int n = tid >> 5;

    const float* xb = g_att + (((size_t)b * DIMC) << 14) + (row << 7);
    for (int idx = tid; idx < 96 * 128; idx += 256) {
        int c = idx >> 7, px = idx & 127;
        x_sh[idx] = xb[(((size_t)c) << 14) + px];
    }
    for (int idx = tid; idx < 96 * 96; idx += 256) w_sh[idx] = w[idx];
    __syncthreads();

    float acc[4][12];
    #pragma unroll
    for (int i = 0; i < 4; ++i)
        #pragma unroll
        for (int u = 0; u < 12; ++u) acc[i][u] = 0.0f;

    for (int k = 0; k < 96; ++k) {
        float4 a4 = *(const float4*)&x_sh[(k << 7) + m * 4];
        #pragma unroll
        for (int u = 0; u < 12; ++u) {
            float bw = w_sh[(n * 12 + u) * 96 + k];
            acc[0][u] = fmaf(a4.x, bw, acc[0][u]);
            acc[1][u] = fmaf(a4.y, bw, acc[1][u]);
            acc[2][u] = fmaf(a4.z, bw, acc[2][u]);
            acc[3][u] = fmaf(a4.w, bw, acc[3][u]);
        }
    }

    #pragma unroll
    for (int u = 0; u < 12; ++u) {
        int oc = n * 12 + u;
        float bs = bias[oc];
        float4 v4;
        v4.x = acc[0][u] + bs; v4.y = acc[1][u] + bs;
        v4.z = acc[2][u] + bs; v4.w = acc[3][u] + bs;
        *(float4*)(out + ((((size_t)b * DIMC) + oc) << 14) + (row << 7) + m * 4) = v4;
    }
}

// ---------------- launch ---------------------------------------------------
extern "C" void kernel_launch(void* const* d_in, const int* in_sizes, int n_in,
                              void* d_out, int out_size) {
    const float* x      = (const float*)d_in[0];
    const float* qkv_w  = (const float*)d_in[1];
    const float* qkv_b  = (const float*)d_in[2];
    const float* attn_w = (const float*)d_in[3];
    const float* attn_b = (const float*)d_in[4];
    const float* proj_w = (const float*)d_in[5];
    const float* proj_b = (const float*)d_in[6];
    float* out = (float*)d_out;

    const int SMEM_GEMM = (96 * 128 + 96 * 96) * 4;   // 86016 B (k1/k3)
    const int SMEM_K2   = (256 * 50 + 14 * 40 * 8) * 4; // 69120 B

    cudaFuncSetAttribute(k1_qkv,  cudaFuncAttributeMaxDynamicSharedMemorySize, SMEM_GEMM);
    cudaFuncSetAttribute(k2_attn, cudaFuncAttributeMaxDynamicSharedMemorySize, SMEM_K2);
    cudaFuncSetAttribute(k3_proj, cudaFuncAttributeMaxDynamicSharedMemorySize, SMEM_GEMM);

    k0_prep<<<(64 * WSQ * TPAD + 255) / 256, 256>>>(attn_w);
    k1_qkv<<<dim3(128, BATCH), 256, SMEM_GEMM>>>(x, qkv_w, qkv_b);
    k2_attn<<<dim3(4, 16, NBH), 256, SMEM_K2>>>(attn_b);
    k3_proj<<<dim3(128, BATCH), 256, SMEM_GEMM>>>(proj_w, proj_b, out);
}

// round 2
// speedup vs baseline: 1.0004x; 1.0004x over previous
#include <cuda_runtime.h>

#define BATCH 4
#define DIMC 96
#define HEADS 3
#define NBH 12            // BATCH*HEADS
#define WSQ 49
#define TPAD 56
#define QK_SCALE 0.17677669529663687f   // 32^-0.5

// ---------------- scratch (device globals; no allocation allowed) ----------
__device__ float g_qk [(size_t)NBH * 64 * 128 * 128];   // [bh][64: q*s | k][y][x]
__device__ float g_v  [(size_t)NBH * 32 * 128 * 128];   // [bh][32][y][x]
__device__ float g_att[(size_t)BATCH * DIMC * 128 * 128];
__device__ float g_w2 [64 * WSQ * TPAD];                // [c][s][t(pad 56)]

// ---------------- K0: repack attn_w [t][c][s] -> [c][s][t] (t padded) ------
__global__ void k0_prep(const float* __restrict__ attn_w) {
    int idx = blockIdx.x * 256 + threadIdx.x;
    if (idx >= 64 * WSQ * TPAD) return;
    int c = idx / (WSQ * TPAD);
    int r = idx - c * (WSQ * TPAD);
    int s = r / TPAD;
    int t = r - s * TPAD;
    g_w2[idx] = (t < WSQ) ? attn_w[(t * 64 + c) * WSQ + s] : 0.0f;
}

// ---------------- K1: 1x1 qkv conv, write qk (q pre-scaled) and v ----------
// block = one image row (128 px), loops 3 chunks of 96 oc (q,k,v)
__global__ __launch_bounds__(256, 2) void k1_qkv(const float* __restrict__ x,
                                                 const float* __restrict__ w,
                                                 const float* __restrict__ bias) {
    extern __shared__ float smem[];
    float* x_sh = smem;             // [96][128]
    float* w_sh = smem + 96 * 128;  // [96][96]
    const int tid = threadIdx.x;
    const int row = blockIdx.x;
    const int b   = blockIdx.y;
    const int m = tid & 31;   // pixel group: px = m*4 .. m*4+3
    const int n = tid >> 5;   // oc group:   oc96 = n*12 .. n*12+11

    const float* xb = x + (((size_t)b * DIMC) << 14) + (row << 7);
    for (int idx = tid; idx < 96 * 128; idx += 256) {
        int c = idx >> 7, px = idx & 127;
        x_sh[idx] = xb[(((size_t)c) << 14) + px];
    }

    for (int chunk = 0; chunk < 3; ++chunk) {   // chunk 0=q 1=k 2=v
        __syncthreads();
        const float* wsrc = w + chunk * 96 * 96;
        for (int idx = tid; idx < 96 * 96; idx += 256) w_sh[idx] = wsrc[idx];
        __syncthreads();

        float acc[4][12];
        #pragma unroll
        for (int i = 0; i < 4; ++i)
            #pragma unroll
            for (int u = 0; u < 12; ++u) acc[i][u] = 0.0f;

        for (int k = 0; k < 96; ++k) {
            float4 a4 = *(const float4*)&x_sh[(k << 7) + m * 4];
            #pragma unroll
            for (int u = 0; u < 12; ++u) {
                float bw = w_sh[(n * 12 + u) * 96 + k];   // warp-uniform broadcast
                acc[0][u] = fmaf(a4.x, bw, acc[0][u]);
                acc[1][u] = fmaf(a4.y, bw, acc[1][u]);
                acc[2][u] = fmaf(a4.z, bw, acc[2][u]);
                acc[3][u] = fmaf(a4.w, bw, acc[3][u]);
            }
        }

        #pragma unroll
        for (int u = 0; u < 12; ++u) {
            int oc96 = n * 12 + u;
            int head = oc96 >> 5, ch = oc96 & 31;
            int bh = b * HEADS + head;
            float bs = bias[chunk * 96 + oc96];
            float4 v4;
            v4.x = acc[0][u] + bs; v4.y = acc[1][u] + bs;
            v4.z = acc[2][u] + bs; v4.w = acc[3][u] + bs;
            float* dst;
            if (chunk == 0) {
                v4.x *= QK_SCALE; v4.y *= QK_SCALE; v4.z *= QK_SCALE; v4.w *= QK_SCALE;
                dst = g_qk + ((((size_t)bh * 64) + ch) << 14) + (row << 7) + m * 4;
            } else if (chunk == 1) {
                dst = g_qk + ((((size_t)bh * 64) + 32 + ch) << 14) + (row << 7) + m * 4;
            } else {
                dst = g_v + ((((size_t)bh * 32) + ch) << 14) + (row << 7) + m * 4;
            }
            *(float4*)dst = v4;
        }
    }
}

// ---------------- K2: logits conv (implicit GEMM) + softmax + attn.V -------
// block: 1 bh, 8x32 pixel tile, 256 threads.
// GEMM: M=256 px, N=56 (49 real t), K=64c*49s.
// thread = (g pixel-group of 8 px, n t-group of 7 t); tid = g*8 + n
//   -> warp has 4 g values x 8 n values: A reads broadcast, B reads 8 banks.
#define QKSH_ROW 39           // 38 halo cols + 1 pad (conflict-free A reads)
#define QKSH_C   546          // 14*39
#define HALO_N   532          // 14*38

__global__ __launch_bounds__(256, 2) void k2_attn(const float* __restrict__ attn_b) {
    extern __shared__ float smem[];
    float* qk_sh     = smem;                  // phase A: [8][14][39] = 4368
    float* B_sh      = smem + 8 * QKSH_C;     // phase A: [49][56]    = 2744
    float* logits_sh = smem;                  // phase B: [256][50]   = 12800
    float* v_sh      = smem + 256 * 50;       // phase B: [14][40][8] = 4480

    const int tid = threadIdx.x;
    const int bh  = blockIdx.z;
    const int ty0 = blockIdx.y * 8;
    const int tx0 = blockIdx.x * 32;
    const int n   = tid & 7;          // t-group: t = n*7 .. n*7+6
    const int g   = tid >> 3;         // pixel group
    const int gy  = g >> 2;           // tile y (0..7)
    const int gx0 = (g & 3) * 8;      // tile x base (0,8,16,24)

    float acc[8][7];
    #pragma unroll
    for (int j = 0; j < 8; ++j)
        #pragma unroll
        for (int tt = 0; tt < 7; ++tt) acc[j][tt] = 0.0f;

    for (int cblk = 0; cblk < 8; ++cblk) {
        __syncthreads();
        // load qk halo for 8 channels (zero-padded borders)
        for (int idx = tid; idx < 8 * HALO_N; idx += 256) {
            int cc = idx / HALO_N;
            int r  = idx - cc * HALO_N;
            int hy = r / 38, hx = r - hy * 38;
            int gyy = ty0 - 3 + hy, gxx = tx0 - 3 + hx;
            float val = 0.0f;
            if ((unsigned)gyy < 128u && (unsigned)gxx < 128u)
                val = g_qk[((((size_t)bh * 64) + cblk * 8 + cc) << 14) + (gyy << 7) + gxx];
            qk_sh[cc * QKSH_C + hy * QKSH_ROW + hx] = val;
        }
        for (int c = 0; c < 8; ++c) {
            __syncthreads();
            const float* wsrc = g_w2 + (cblk * 8 + c) * (WSQ * TPAD);
            for (int idx = tid; idx < WSQ * TPAD; idx += 256) B_sh[idx] = wsrc[idx];
            __syncthreads();
            const float* abase = qk_sh + c * QKSH_C + gy * QKSH_ROW + gx0;
            #pragma unroll 1
            for (int dy = 0; dy < 7; ++dy) {
                float av[14];                      // A row cached: reused across dx
                const float* arow = abase + dy * QKSH_ROW;
                #pragma unroll
                for (int i = 0; i < 14; ++i) av[i] = arow[i];
                #pragma unroll
                for (int dx = 0; dx < 7; ++dx) {
                    const float* brow = B_sh + (dy * 7 + dx) * TPAD + n * 7;
                    float bv[7];
                    #pragma unroll
                    for (int tt = 0; tt < 7; ++tt) bv[tt] = brow[tt];
                    #pragma unroll
                    for (int j = 0; j < 8; ++j)
                        #pragma unroll
                        for (int tt = 0; tt < 7; ++tt)
                            acc[j][tt] = fmaf(av[dx + j], bv[tt], acc[j][tt]);
                }
            }
        }
    }

    // per-thread bias values for its t range
    float bb[7];
    #pragma unroll
    for (int tt = 0; tt < 7; ++tt) {
        int t = n * 7 + tt;
        bb[tt] = (t < WSQ) ? attn_b[t] : 0.0f;
    }

    __syncthreads();   // compute done -> reuse smem for logits
    #pragma unroll
    for (int j = 0; j < 8; ++j) {
        int p = (gy << 5) + gx0 + j;
        #pragma unroll
        for (int tt = 0; tt < 7; ++tt) {
            int t = n * 7 + tt;
            if (t < WSQ) logits_sh[p * 50 + t] = acc[j][tt] + bb[tt];
        }
    }
    __syncthreads();

    // per-pixel softmax: thread tid owns pixel tid
    const int py = tid >> 5, px = tid & 31;
    float lg[WSQ];
    float mx = -1e30f;
    #pragma unroll
    for (int t = 0; t < WSQ; ++t) { lg[t] = logits_sh[tid * 50 + t]; mx = fmaxf(mx, lg[t]); }
    float sum = 0.0f;
    #pragma unroll
    for (int t = 0; t < WSQ; ++t) { lg[t] = __expf(lg[t] - mx); sum += lg[t]; }
    float inv = 1.0f / sum;
    #pragma unroll
    for (int t = 0; t < WSQ; ++t) lg[t] *= inv;

    const int b    = bh / HEADS;
    const int head = bh - b * HEADS;

    // attn . V  (v halo in chunks of 8 channels, channel-fastest smem for vec4 reads)
    for (int vcblk = 0; vcblk < 4; ++vcblk) {
        __syncthreads();
        for (int idx = tid; idx < 8 * HALO_N; idx += 256) {
            int cc = idx / HALO_N;
            int r  = idx - cc * HALO_N;
            int hy = r / 38, hx = r - hy * 38;
            int gyy = ty0 - 3 + hy, gxx = tx0 - 3 + hx;
            float val = 0.0f;
            if ((unsigned)gyy < 128u && (unsigned)gxx < 128u)
                val = g_v[((((size_t)bh * 32) + vcblk * 8 + cc) << 14) + (gyy << 7) + gxx];
            v_sh[(hy * 40 + hx) * 8 + cc] = val;
        }
        __syncthreads();

        float o[8];
        #pragma unroll
        for (int vc = 0; vc < 8; ++vc) o[vc] = 0.0f;
        #pragma unroll
        for (int dy = 0; dy < 7; ++dy) {
            #pragma unroll
            for (int dx = 0; dx < 7; ++dx) {
                float a = lg[dy * 7 + dx];
                const float4* vp = (const float4*)&v_sh[((py + dy) * 40 + px + dx) * 8];
                float4 v0 = vp[0], v1 = vp[1];
                o[0] = fmaf(a, v0.x, o[0]); o[1] = fmaf(a, v0.y, o[1]);
                o[2] = fmaf(a, v0.z, o[2]); o[3] = fmaf(a, v0.w, o[3]);
                o[4] = fmaf(a, v1.x, o[4]); o[5] = fmaf(a, v1.y, o[5]);
                o[6] = fmaf(a, v1.z, o[6]); o[7] = fmaf(a, v1.w, o[7]);
            }
        }
        #pragma unroll
        for (int vc = 0; vc < 8; ++vc)
            g_att[((((size_t)b * DIMC) + head * 32 + vcblk * 8 + vc) << 14)
                  + ((ty0 + py) << 7) + (tx0 + px)] = o[vc];
    }
}

// ---------------- K3: 1x1 proj -> d_out ------------------------------------
__global__ __launch_bounds__(256, 2) void k3_proj(const float* __restrict__ w,
                                                  const float* __restrict__ bias,
                                                  float* __restrict__ out) {
    extern __shared__ float smem[];
    float* x_sh = smem;             // [96][128]
    float* w_sh = smem + 96 * 128;  // [96][96]
    const int tid = threadIdx.x;
    const int row = blockIdx.x;
    const int b   = blockIdx.y;
    const int m = tid & 31;
    const int n = tid >> 5;

    const float* xb = g_att + (((size_t)b * DIMC) << 14) + (row << 7);
    for (int idx = tid; idx < 96 * 128; idx += 256) {
        int c = idx >> 7, px = idx & 127;
        x_sh[idx] = xb[(((size_t)c) << 14) + px];
    }
    for (int idx = tid; idx < 96 * 96; idx += 256) w_sh[idx] = w[idx];
    __syncthreads();

    float acc[4][12];
    #pragma unroll
    for (int i = 0; i < 4; ++i)
        #pragma unroll
        for (int u = 0; u < 12; ++u) acc[i][u] = 0.0f;

    for (int k = 0; k < 96; ++k) {
        float4 a4 = *(const float4*)&x_sh[(k << 7) + m * 4];
        #pragma unroll
        for (int u = 0; u < 12; ++u) {
            float bw = w_sh[(n * 12 + u) * 96 + k];
            acc[0][u] = fmaf(a4.x, bw, acc[0][u]);
            acc[1][u] = fmaf(a4.y, bw, acc[1][u]);
            acc[2][u] = fmaf(a4.z, bw, acc[2][u]);
            acc[3][u] = fmaf(a4.w, bw, acc[3][u]);
        }
    }

    #pragma unroll
    for (int u = 0; u < 12; ++u) {
        int oc = n * 12 + u;
        float bs = bias[oc];
        float4 v4;
        v4.x = acc[0][u] + bs; v4.y = acc[1][u] + bs;
        v4.z = acc[2][u] + bs; v4.w = acc[3][u] + bs;
        *(float4*)(out + ((((size_t)b * DIMC) + oc) << 14) + (row << 7) + m * 4) = v4;
    }
}

// ---------------- launch ---------------------------------------------------
extern "C" void kernel_launch(void* const* d_in, const int* in_sizes, int n_in,
                              void* d_out, int out_size) {
    const float* x      = (const float*)d_in[0];
    const float* qkv_w  = (const float*)d_in[1];
    const float* qkv_b  = (const float*)d_in[2];
    const float* attn_w = (const float*)d_in[3];
    const float* attn_b = (const float*)d_in[4];
    const float* proj_w = (const float*)d_in[5];
    const float* proj_b = (const float*)d_in[6];
    float* out = (float*)d_out;

    const int SMEM_GEMM = (96 * 128 + 96 * 96) * 4;   // 86016 B (k1/k3)
    const int SMEM_K2   = (256 * 50 + 14 * 40 * 8) * 4; // 69120 B

    cudaFuncSetAttribute(k1_qkv,  cudaFuncAttributeMaxDynamicSharedMemorySize, SMEM_GEMM);
    cudaFuncSetAttribute(k2_attn, cudaFuncAttributeMaxDynamicSharedMemorySize, SMEM_K2);
    cudaFuncSetAttribute(k3_proj, cudaFuncAttributeMaxDynamicSharedMemorySize, SMEM_GEMM);

    k0_prep<<<(64 * WSQ * TPAD + 255) / 256, 256>>>(attn_w);
    k1_qkv<<<dim3(128, BATCH), 256, SMEM_GEMM>>>(x, qkv_w, qkv_b);
    k2_attn<<<dim3(4, 16, NBH), 256, SMEM_K2>>>(attn_b);
    k3_proj<<<dim3(128, BATCH), 256, SMEM_GEMM>>>(proj_w, proj_b, out);
}

// round 3
// speedup vs baseline: 2.5461x; 2.5450x over previous
#include <cuda_runtime.h>

#define BATCH 4
#define DIMC 96
#define HEADS 3
#define NBH 12            // BATCH*HEADS
#define WSQ 49
#define QK_SCALE 0.17677669529663687f   // 32^-0.5

// k2 geometry
#define HX 38
#define HY 14
#define CP 36                         // channel pad (conflict-free A frags)
#define HALO_FL (HY * HX * CP)        // 19152 floats
#define BTILE 1792                    // 32 ch * 56 t
#define TP 56                         // t padded
#define HALO_N 532                    // 14*38 (AV phase)

// ---------------- scratch (device globals; no allocation allowed) ----------
__device__ float g_qk [(size_t)NBH * 64 * 128 * 128];   // [bh][64: q*s | k][y][x] (tf32-rounded)
__device__ float g_v  [(size_t)NBH * 32 * 128 * 128];   // [bh][32][y][x]
__device__ float g_att[(size_t)BATCH * DIMC * 128 * 128];
__device__ float g_w2 [(size_t)WSQ * 64 * TP];          // [s][c][t(pad 56)] tf32-rounded

__device__ __forceinline__ float to_tf32(float x) {
    unsigned u;
    asm("cvt.rna.tf32.f32 %0, %1;" : "=r"(u) : "f"(x));
    return __uint_as_float(u);
}

// ---------------- K0: repack attn_w [t][c][s] -> [s][c][t pad], tf32 -------
__global__ void k0_prep(const float* __restrict__ attn_w) {
    int idx = blockIdx.x * 256 + threadIdx.x;
    if (idx >= WSQ * 64 * TP) return;
    int s = idx / (64 * TP);
    int rem = idx - s * (64 * TP);
    int c = rem / TP;
    int t = rem - c * TP;
    g_w2[idx] = (t < WSQ) ? to_tf32(attn_w[(t * 64 + c) * WSQ + s]) : 0.0f;
}

// ---------------- K1: 1x1 qkv conv, write qk (q pre-scaled, tf32) and v ----
__global__ __launch_bounds__(256, 2) void k1_qkv(const float* __restrict__ x,
                                                 const float* __restrict__ w,
                                                 const float* __restrict__ bias) {
    extern __shared__ float smem[];
    float* x_sh = smem;             // [96][128]
    float* w_sh = smem + 96 * 128;  // [96][96]
    const int tid = threadIdx.x;
    const int row = blockIdx.x;
    const int b   = blockIdx.y;
    const int m = tid & 31;   // pixel group: px = m*4 .. m*4+3
    const int n = tid >> 5;   // oc group:   oc96 = n*12 .. n*12+11

    const float* xb = x + (((size_t)b * DIMC) << 14) + (row << 7);
    for (int idx = tid; idx < 96 * 128; idx += 256) {
        int c = idx >> 7, px = idx & 127;
        x_sh[idx] = xb[(((size_t)c) << 14) + px];
    }

    for (int chunk = 0; chunk < 3; ++chunk) {   // chunk 0=q 1=k 2=v
        __syncthreads();
        const float* wsrc = w + chunk * 96 * 96;
        for (int idx = tid; idx < 96 * 96; idx += 256) w_sh[idx] = wsrc[idx];
        __syncthreads();

        float acc[4][12];
        #pragma unroll
        for (int i = 0; i < 4; ++i)
            #pragma unroll
            for (int u = 0; u < 12; ++u) acc[i][u] = 0.0f;

        for (int k = 0; k < 96; ++k) {
            float4 a4 = *(const float4*)&x_sh[(k << 7) + m * 4];
            #pragma unroll
            for (int u = 0; u < 12; ++u) {
                float bw = w_sh[(n * 12 + u) * 96 + k];
                acc[0][u] = fmaf(a4.x, bw, acc[0][u]);
                acc[1][u] = fmaf(a4.y, bw, acc[1][u]);
                acc[2][u] = fmaf(a4.z, bw, acc[2][u]);
                acc[3][u] = fmaf(a4.w, bw, acc[3][u]);
            }
        }

        #pragma unroll
        for (int u = 0; u < 12; ++u) {
            int oc96 = n * 12 + u;
            int head = oc96 >> 5, ch = oc96 & 31;
            int bh = b * HEADS + head;
            float bs = bias[chunk * 96 + oc96];
            float4 v4;
            v4.x = acc[0][u] + bs; v4.y = acc[1][u] + bs;
            v4.z = acc[2][u] + bs; v4.w = acc[3][u] + bs;
            float* dst;
            if (chunk == 0) {
                v4.x = to_tf32(v4.x * QK_SCALE); v4.y = to_tf32(v4.y * QK_SCALE);
                v4.z = to_tf32(v4.z * QK_SCALE); v4.w = to_tf32(v4.w * QK_SCALE);
                dst = g_qk + ((((size_t)bh * 64) + ch) << 14) + (row << 7) + m * 4;
            } else if (chunk == 1) {
                v4.x = to_tf32(v4.x); v4.y = to_tf32(v4.y);
                v4.z = to_tf32(v4.z); v4.w = to_tf32(v4.w);
                dst = g_qk + ((((size_t)bh * 64) + 32 + ch) << 14) + (row << 7) + m * 4;
            } else {
                dst = g_v + ((((size_t)bh * 32) + ch) << 14) + (row << 7) + m * 4;
            }
            *(float4*)dst = v4;
        }
    }
}

// ---------------- K2: logits conv via tf32 tensor cores + softmax + attn.V -
// Per tap s (49 shifted 1x1 GEMMs): M=256 px, N=56(49), K=64 (2 passes of 32).
// halo: [y][x][c pad36] channel-fastest -> conflict-free A fragment LDS.
// B: [32c][56t] double-buffered smem, conflict-free frag LDS (stride 56).
// Warp w: mgrp=w&3 -> 4 M-tiles (64 px), ngrp=w>>2 -> 4 or 3 N-tiles.
__global__ __launch_bounds__(256, 2) void k2_attn(const float* __restrict__ attn_b) {
    extern __shared__ float smem[];
    float* halo      = smem;                 // [14][38][36] = 19152 fl
    float* Bb        = smem + HALO_FL;       // 2 x 1792 fl
    float* logits_sh = smem;                 // phase B: [256][50]
    float* v_sh      = smem + 256 * 50;      // phase B: [14][40][8]

    const int tid  = threadIdx.x;
    const int lane = tid & 31, wid = tid >> 5;
    const int q = lane >> 2, r = lane & 3;
    const int mgrp = wid & 3, ngrp = wid >> 2;
    const int NTL  = ngrp ? 3 : 4;           // ngrp0: nt 0-3, ngrp1: nt 4-6
    const int bh  = blockIdx.z;
    const int ty0 = blockIdx.y * 8;
    const int tx0 = blockIdx.x * 32;

    int RB[4];
    #pragma unroll
    for (int i = 0; i < 4; ++i) {
        int mt = mgrp * 4 + i;
        int p0 = mt * 16 + q;
        int py = p0 >> 5, px = p0 & 31;
        RB[i] = (py * HX + px) * CP;
    }

    float acc[4][4][4];
    #pragma unroll
    for (int i = 0; i < 4; ++i)
        #pragma unroll
        for (int j = 0; j < 4; ++j)
            #pragma unroll
            for (int e = 0; e < 4; ++e) acc[i][j][e] = 0.0f;

    for (int pass = 0; pass < 2; ++pass) {
        __syncthreads();
        // load 32-channel halo, channel-fastest with pad 36
        const float* src = g_qk + (((size_t)bh * 64 + pass * 32) << 14);
        for (int idx = tid; idx < 32 * HY * HX; idx += 256) {
            int c  = idx / (HY * HX);
            int yx = idx - c * (HY * HX);
            int y = yx / HX, xx = yx - y * HX;
            int gy = ty0 - 3 + y, gx = tx0 - 3 + xx;
            float val = 0.0f;
            if ((unsigned)gy < 128u && (unsigned)gx < 128u)
                val = src[(((size_t)c) << 14) + (gy << 7) + gx];
            halo[yx * CP + c] = val;
        }
        __syncthreads();
        // prologue: B tile for tap 0
        {
            const float* wsrc = g_w2 + (size_t)(pass * 32) * TP;
            #pragma unroll
            for (int u = 0; u < 7; ++u) Bb[tid + u * 256] = wsrc[tid + u * 256];
        }
        __syncthreads();

        for (int s = 0; s < WSQ; ++s) {
            float* cur = Bb + (s & 1) * BTILE;
            float* nxt = Bb + ((s + 1) & 1) * BTILE;
            float tmp[7];
            if (s < WSQ - 1) {
                const float* wsrc = g_w2 + ((size_t)(s + 1) * 64 + pass * 32) * TP;
                #pragma unroll
                for (int u = 0; u < 7; ++u) tmp[u] = wsrc[tid + u * 256];
            }
            int dy = s / 7, dx = s - dy * 7;
            const float* abase = halo + (dy * HX + dx) * CP + r;

            #pragma unroll
            for (int kt = 0; kt < 4; ++kt) {
                unsigned a[4][4];
                #pragma unroll
                for (int i = 0; i < 4; ++i) {
                    const float* ap = abase + RB[i] + kt * 8;
                    a[i][0] = __float_as_uint(ap[0]);            // (row q,   col r)
                    a[i][1] = __float_as_uint(ap[8 * CP]);       // (row q+8, col r)
                    a[i][2] = __float_as_uint(ap[4]);            // (row q,   col r+4)
                    a[i][3] = __float_as_uint(ap[8 * CP + 4]);   // (row q+8, col r+4)
                }
                #pragma unroll
                for (int j = 0; j < 4; ++j) {
                    if (j >= NTL) break;
                    int nt = ngrp * 4 + j;
                    const float* bp = cur + (kt * 8 + r) * TP + nt * 8 + q;
                    unsigned b0 = __float_as_uint(bp[0]);
                    unsigned b1 = __float_as_uint(bp[4 * TP]);
                    #pragma unroll
                    for (int i = 0; i < 4; ++i) {
                        asm volatile(
                            "mma.sync.aligned.m16n8k8.row.col.f32.tf32.tf32.f32 "
                            "{%0,%1,%2,%3},{%4,%5,%6,%7},{%8,%9},{%0,%1,%2,%3};"
                            : "+f"(acc[i][j][0]), "+f"(acc[i][j][1]),
                              "+f"(acc[i][j][2]), "+f"(acc[i][j][3])
                            : "r"(a[i][0]), "r"(a[i][1]), "r"(a[i][2]), "r"(a[i][3]),
                              "r"(b0), "r"(b1));
                    }
                }
            }
            if (s < WSQ - 1) {
                #pragma unroll
                for (int u = 0; u < 7; ++u) nxt[tid + u * 256] = tmp[u];
            }
            __syncthreads();
        }
    }

    // ---- write logits (+bias) to smem (reuses halo region; synced above) ----
    #pragma unroll
    for (int i = 0; i < 4; ++i) {
        int p0 = (mgrp * 4 + i) * 16 + q;
        #pragma unroll
        for (int j = 0; j < 4; ++j) {
            if (j >= NTL) break;
            int nt = ngrp * 4 + j;
            int t0 = nt * 8 + r * 2;
            if (t0 < WSQ) {
                float bb = attn_b[t0];
                logits_sh[p0 * 50 + t0]       = acc[i][j][0] + bb;
                logits_sh[(p0 + 8) * 50 + t0] = acc[i][j][2] + bb;
            }
            if (t0 + 1 < WSQ) {
                float bb = attn_b[t0 + 1];
                logits_sh[p0 * 50 + t0 + 1]       = acc[i][j][1] + bb;
                logits_sh[(p0 + 8) * 50 + t0 + 1] = acc[i][j][3] + bb;
            }
        }
    }
    __syncthreads();

    // ---- per-pixel softmax: thread tid owns pixel tid ----
    const int py = tid >> 5, px = tid & 31;
    float lg[WSQ];
    float mx = -1e30f;
    #pragma unroll
    for (int t = 0; t < WSQ; ++t) { lg[t] = logits_sh[tid * 50 + t]; mx = fmaxf(mx, lg[t]); }
    float sum = 0.0f;
    #pragma unroll
    for (int t = 0; t < WSQ; ++t) { lg[t] = __expf(lg[t] - mx); sum += lg[t]; }
    float inv = 1.0f / sum;
    #pragma unroll
    for (int t = 0; t < WSQ; ++t) lg[t] *= inv;

    const int b    = bh / HEADS;
    const int head = bh - b * HEADS;

    // ---- attn . V ----
    for (int vcblk = 0; vcblk < 4; ++vcblk) {
        __syncthreads();
        for (int idx = tid; idx < 8 * HALO_N; idx += 256) {
            int cc = idx / HALO_N;
            int rr = idx - cc * HALO_N;
            int hy = rr / HX, hx = rr - hy * HX;
            int gyy = ty0 - 3 + hy, gxx = tx0 - 3 + hx;
            float val = 0.0f;
            if ((unsigned)gyy < 128u && (unsigned)gxx < 128u)
                val = g_v[((((size_t)bh * 32) + vcblk * 8 + cc) << 14) + (gyy << 7) + gxx];
            v_sh[(hy * 40 + hx) * 8 + cc] = val;
        }
        __syncthreads();

        float o[8];
        #pragma unroll
        for (int vc = 0; vc < 8; ++vc) o[vc] = 0.0f;
        #pragma unroll
        for (int dy = 0; dy < 7; ++dy) {
            #pragma unroll
            for (int dx = 0; dx < 7; ++dx) {
                float a = lg[dy * 7 + dx];
                const float4* vp = (const float4*)&v_sh[((py + dy) * 40 + px + dx) * 8];
                float4 v0 = vp[0], v1 = vp[1];
                o[0] = fmaf(a, v0.x, o[0]); o[1] = fmaf(a, v0.y, o[1]);
                o[2] = fmaf(a, v0.z, o[2]); o[3] = fmaf(a, v0.w, o[3]);
                o[4] = fmaf(a, v1.x, o[4]); o[5] = fmaf(a, v1.y, o[5]);
                o[6] = fmaf(a, v1.z, o[6]); o[7] = fmaf(a, v1.w, o[7]);
            }
        }
        #pragma unroll
        for (int vc = 0; vc < 8; ++vc)
            g_att[((((size_t)b * DIMC) + head * 32 + vcblk * 8 + vc) << 14)
                  + ((ty0 + py) << 7) + (tx0 + px)] = o[vc];
    }
}

// ---------------- K3: 1x1 proj -> d_out ------------------------------------
__global__ __launch_bounds__(256, 2) void k3_proj(const float* __restrict__ w,
                                                  const float* __restrict__ bias,
                                                  float* __restrict__ out) {
    extern __shared__ float smem[];
    float* x_sh = smem;             // [96][128]
    float* w_sh = smem + 96 * 128;  // [96][96]
    const int tid = threadIdx.x;
    const int row = blockIdx.x;
    const int b   = blockIdx.y;
    const int m = tid & 31;
    const int n = tid >> 5;

    const float* xb = g_att + (((size_t)b * DIMC) << 14) + (row << 7);
    for (int idx = tid; idx < 96 * 128; idx += 256) {
        int c = idx >> 7, px = idx & 127;
        x_sh[idx] = xb[(((size_t)c) << 14) + px];
    }
    for (int idx = tid; idx < 96 * 96; idx += 256) w_sh[idx] = w[idx];
    __syncthreads();

    float acc[4][12];
    #pragma unroll
    for (int i = 0; i < 4; ++i)
        #pragma unroll
        for (int u = 0; u < 12; ++u) acc[i][u] = 0.0f;

    for (int k = 0; k < 96; ++k) {
        float4 a4 = *(const float4*)&x_sh[(k << 7) + m * 4];
        #pragma unroll
        for (int u = 0; u < 12; ++u) {
            float bw = w_sh[(n * 12 + u) * 96 + k];
            acc[0][u] = fmaf(a4.x, bw, acc[0][u]);
            acc[1][u] = fmaf(a4.y, bw, acc[1][u]);
            acc[2][u] = fmaf(a4.z, bw, acc[2][u]);
            acc[3][u] = fmaf(a4.w, bw, acc[3][u]);
        }
    }

    #pragma unroll
    for (int u = 0; u < 12; ++u) {
        int oc = n * 12 + u;
        float bs = bias[oc];
        float4 v4;
        v4.x = acc[0][u] + bs; v4.y = acc[1][u] + bs;
        v4.z = acc[2][u] + bs; v4.w = acc[3][u] + bs;
        *(float4*)(out + ((((size_t)b * DIMC) + oc) << 14) + (row << 7) + m * 4) = v4;
    }
}

// ---------------- launch ---------------------------------------------------
extern "C" void kernel_launch(void* const* d_in, const int* in_sizes, int n_in,
                              void* d_out, int out_size) {
    const float* x      = (const float*)d_in[0];
    const float* qkv_w  = (const float*)d_in[1];
    const float* qkv_b  = (const float*)d_in[2];
    const float* attn_w = (const float*)d_in[3];
    const float* attn_b = (const float*)d_in[4];
    const float* proj_w = (const float*)d_in[5];
    const float* proj_b = (const float*)d_in[6];
    float* out = (float*)d_out;

    const int SMEM_GEMM = (96 * 128 + 96 * 96) * 4;         // 86016 B (k1/k3)
    const int SMEM_K2   = (HALO_FL + 2 * BTILE) * 4;        // 90944 B

    cudaFuncSetAttribute(k1_qkv,  cudaFuncAttributeMaxDynamicSharedMemorySize, SMEM_GEMM);
    cudaFuncSetAttribute(k2_attn, cudaFuncAttributeMaxDynamicSharedMemorySize, SMEM_K2);
    cudaFuncSetAttribute(k3_proj, cudaFuncAttributeMaxDynamicSharedMemorySize, SMEM_GEMM);

    k0_prep<<<(WSQ * 64 * TP + 255) / 256, 256>>>(attn_w);
    k1_qkv<<<dim3(128, BATCH), 256, SMEM_GEMM>>>(x, qkv_w, qkv_b);
    k2_attn<<<dim3(4, 16, NBH), 256, SMEM_K2>>>(attn_b);
    k3_proj<<<dim3(128, BATCH), 256, SMEM_GEMM>>>(proj_w, proj_b, out);
}

// round 7
// speedup vs baseline: 3.8814x; 1.5245x over previous
#include <cuda_runtime.h>
#include <cuda_fp16.h>
#include <cstdint>

#define BATCH 4
#define DIMC 96
#define HEADS 3
#define NBH 12
#define WSQ 49
#define QK_SCALE 0.17677669529663687f

// ---- k2 geometry ----
#define HPX 72                 // fp16 per pixel (64 data + 8 pad) -> conflict-free ldmatrix
#define PXB 144                // bytes per pixel
#define HALO_PX 532            // 14*38 halo pixels
#define HALO_BYTES (HALO_PX * PXB)   // 76608
#define BOFF2 HALO_BYTES
#define BTAPU2 896             // uint2 per tap of B fragments: 4 ks * 7 nt * 32 lanes
#define SMEM_K2 (HALO_BYTES + 2 * BTAPU2 * 8)   // 90944
#define HALO_N 532

// ---------------- scratch (device globals) ----------------
__device__ __half g_qkh[(size_t)NBH * 128 * 128 * 64];   // [bh][y][x][64: q*s ch0-31 | k ch32-63]
__device__ float  g_v  [(size_t)NBH * 32 * 128 * 128];   // [bh][32][y][x] planar
__device__ float  g_att[(size_t)BATCH * DIMC * 128 * 128];
__device__ uint2  g_w2f[(size_t)WSQ * BTAPU2];           // B fragments [s][ks][nt][lane]{4 half}

// ---------------- K0: pack attn_w into per-fragment fp16 layout ------------
__global__ void k0_prep(const float* __restrict__ attn_w) {
    int idx = blockIdx.x * 256 + threadIdx.x;
    if (idx >= WSQ * BTAPU2) return;
    int lane = idx & 31;
    int nt   = (idx >> 5) % 7;
    int ks   = ((idx >> 5) / 7) & 3;
    int s    = idx / (32 * 28);
    int n = nt * 8 + (lane >> 2);           // t index
    int k0 = ks * 16 + (lane & 3) * 2;      // c index
    __half h[4];
    #pragma unroll
    for (int ii = 0; ii < 2; ++ii)
        h[ii] = (n < WSQ) ? __float2half(attn_w[(n * 64 + k0 + ii) * WSQ + s]) : __half(0.f);
    #pragma unroll
    for (int ii = 0; ii < 2; ++ii)
        h[2 + ii] = (n < WSQ) ? __float2half(attn_w[(n * 64 + k0 + 8 + ii) * WSQ + s]) : __half(0.f);
    uint2 u;
    u.x = *(const uint32_t*)&h[0];
    u.y = *(const uint32_t*)&h[2];
    g_w2f[idx] = u;
}

// ---------------- K1: 1x1 qkv conv -> fp16 qk (interleaved) + fp32 v -------
__global__ __launch_bounds__(256, 2) void k1_qkv(const float* __restrict__ x,
                                                 const float* __restrict__ w,
                                                 const float* __restrict__ bias) {
    extern __shared__ float smem[];
    float* x_sh = smem;             // [96][128]
    float* w_sh = smem + 96 * 128;  // [96][96]
    const int tid = threadIdx.x;
    const int row = blockIdx.x;
    const int b   = blockIdx.y;
    const int m = tid & 31;   // pixel group px = m*4..+3
    const int n = tid >> 5;   // oc group oc = n*12..+11

    const float* xb = x + (((size_t)b * DIMC) << 14) + (row << 7);
    for (int idx = tid; idx < 96 * 128; idx += 256) {
        int c = idx >> 7, px = idx & 127;
        x_sh[idx] = xb[(((size_t)c) << 14) + px];
    }

    for (int chunk = 0; chunk < 3; ++chunk) {
        __syncthreads();
        const float* wsrc = w + chunk * 96 * 96;
        for (int idx = tid; idx < 96 * 96; idx += 256) w_sh[idx] = wsrc[idx];
        __syncthreads();

        float acc[4][12];
        #pragma unroll
        for (int i = 0; i < 4; ++i)
            #pragma unroll
            for (int u = 0; u < 12; ++u) acc[i][u] = 0.0f;

        for (int k = 0; k < 96; ++k) {
            float4 a4 = *(const float4*)&x_sh[(k << 7) + m * 4];
            #pragma unroll
            for (int u = 0; u < 12; ++u) {
                float bw = w_sh[(n * 12 + u) * 96 + k];
                acc[0][u] = fmaf(a4.x, bw, acc[0][u]);
                acc[1][u] = fmaf(a4.y, bw, acc[1][u]);
                acc[2][u] = fmaf(a4.z, bw, acc[2][u]);
                acc[3][u] = fmaf(a4.w, bw, acc[3][u]);
            }
        }

        if (chunk < 2) {
            // q (scaled) or k -> fp16 interleaved, pairs of channels
            #pragma unroll
            for (int u = 0; u < 12; u += 2) {
                int oc = n * 12 + u;                 // even
                int head = oc >> 5, ch = oc & 31;
                int bh = b * HEADS + head;
                int chs = (chunk == 0) ? ch : 32 + ch;
                float bs0 = bias[chunk * 96 + oc];
                float bs1 = bias[chunk * 96 + oc + 1];
                #pragma unroll
                for (int i = 0; i < 4; ++i) {
                    int px = m * 4 + i;
                    float v0 = acc[i][u] + bs0;
                    float v1 = acc[i][u + 1] + bs1;
                    if (chunk == 0) { v0 *= QK_SCALE; v1 *= QK_SCALE; }
                    __half2 h2 = __floats2half2_rn(v0, v1);
                    *(__half2*)&g_qkh[((((size_t)bh * 128 + row) << 7) + px) * 64 + chs] = h2;
                }
            }
        } else {
            // v -> fp32 planar
            #pragma unroll
            for (int u = 0; u < 12; ++u) {
                int oc = n * 12 + u;
                int head = oc >> 5, ch = oc & 31;
                int bh = b * HEADS + head;
                float bs = bias[2 * 96 + oc];
                float4 v4;
                v4.x = acc[0][u] + bs; v4.y = acc[1][u] + bs;
                v4.z = acc[2][u] + bs; v4.w = acc[3][u] + bs;
                *(float4*)(g_v + ((((size_t)bh * 32) + ch) << 14) + (row << 7) + m * 4) = v4;
            }
        }
    }
}

// ---------------- K2: fp16 mma logits conv + softmax + attn.V --------------
// block: 8x32 px tile, 256 thr. GEMM M=256 N=56 K=64, 49 shifted taps.
// warp wid: mgrp=wid&3 (4 mtiles of 16 px), ngrp=wid>>2 (4 or 3 ntiles of 8 t)
__global__ __launch_bounds__(256, 2) void k2_attn(const float* __restrict__ attn_b) {
    extern __shared__ char smemk2[];
    __half* halo = (__half*)smemk2;
    uint2* Bb = (uint2*)(smemk2 + BOFF2);            // [2][896]
    float* logits_sh = (float*)smemk2;               // phase B: [256][50]
    float* v_sh = (float*)(smemk2 + 256 * 50 * 4);   // phase B: [14][40][8]

    const int tid = threadIdx.x;
    const int lane = tid & 31, wid = tid >> 5;
    const int mgrp = wid & 3, ngrp = wid >> 2;
    const int NTL = ngrp ? 3 : 4;
    const int bh  = blockIdx.z;
    const int ty0 = blockIdx.y * 8;
    const int tx0 = blockIdx.x * 32;

    uint32_t sb;
    { uint64_t t_; asm("cvta.to.shared.u64 %0, %1;" : "=l"(t_) : "l"(smemk2)); sb = (uint32_t)t_; }

    // ---- load qk halo (fp16, pixel stride 72 half) ----
    const uint4* qk4 = (const uint4*)g_qkh;          // 8 uint4 per pixel
    for (int idx = tid; idx < HALO_PX * 8; idx += 256) {
        int pxi = idx >> 3, g = idx & 7;
        int hy = pxi / 38, hx = pxi - hy * 38;
        int gy = ty0 - 3 + hy, gx = tx0 - 3 + hx;
        uint4 val = make_uint4(0, 0, 0, 0);
        if ((unsigned)gy < 128u && (unsigned)gx < 128u)
            val = qk4[((((size_t)bh * 128 + gy) << 7) + gx) * 8 + g];
        *(uint4*)(smemk2 + pxi * PXB + g * 16) = val;
    }
    // prologue: B fragments for tap 0
    for (int i = tid; i < BTAPU2; i += 256) Bb[i] = g_w2f[i];
    __syncthreads();

    // per-lane ldmatrix row address bases (tap offset added later)
    const int mrow = lane & 15;
    const int khalf = lane >> 4;
    uint32_t abase[4];
    #pragma unroll
    for (int i = 0; i < 4; ++i) {
        int p = (mgrp * 4 + i) * 16 + mrow;
        abase[i] = sb + ((p >> 5) * 38 + (p & 31)) * PXB + khalf * 16;
    }

    float acc[4][4][4];
    #pragma unroll
    for (int i = 0; i < 4; ++i)
        #pragma unroll
        for (int j = 0; j < 4; ++j)
            #pragma unroll
            for (int e = 0; e < 4; ++e) acc[i][j][e] = 0.0f;

    for (int s = 0; s < WSQ; ++s) {
        uint2 tb[4];
        if (s < WSQ - 1) {
            #pragma unroll
            for (int u = 0; u < 4; ++u) {
                int i2 = tid + u * 256;
                if (i2 < BTAPU2) tb[u] = g_w2f[(size_t)(s + 1) * BTAPU2 + i2];
            }
        }
        const uint2* cur = Bb + (s & 1) * BTAPU2;
        int dy = s / 7, dx = s - dy * 7;
        uint32_t toff = (uint32_t)(dy * 38 + dx) * PXB;

        #pragma unroll
        for (int ks = 0; ks < 4; ++ks) {
            uint32_t a[4][4];
            #pragma unroll
            for (int i = 0; i < 4; ++i) {
                asm volatile("ldmatrix.sync.aligned.m8n8.x4.shared.b16 {%0,%1,%2,%3}, [%4];"
                    : "=r"(a[i][0]), "=r"(a[i][1]), "=r"(a[i][2]), "=r"(a[i][3])
                    : "r"(abase[i] + toff + ks * 32));
            }
            uint2 bf[4];
            #pragma unroll
            for (int j = 0; j < 4; ++j) {
                if (j >= NTL) break;
                bf[j] = cur[(ks * 7 + ngrp * 4 + j) * 32 + lane];
            }
            #pragma unroll
            for (int j = 0; j < 4; ++j) {
                if (j >= NTL) break;
                #pragma unroll
                for (int i = 0; i < 4; ++i) {
                    asm volatile(
                        "mma.sync.aligned.m16n8k16.row.col.f32.f16.f16.f32 "
                        "{%0,%1,%2,%3},{%4,%5,%6,%7},{%8,%9},{%0,%1,%2,%3};"
                        : "+f"(acc[i][j][0]), "+f"(acc[i][j][1]),
                          "+f"(acc[i][j][2]), "+f"(acc[i][j][3])
                        : "r"(a[i][0]), "r"(a[i][1]), "r"(a[i][2]), "r"(a[i][3]),
                          "r"(bf[j].x), "r"(bf[j].y));
                }
            }
        }
        if (s < WSQ - 1) {
            #pragma unroll
            for (int u = 0; u < 4; ++u) {
                int i2 = tid + u * 256;
                if (i2 < BTAPU2) Bb[((s + 1) & 1) * BTAPU2 + i2] = tb[u];
            }
        }
        __syncthreads();
    }

    // ---- logits (+bias) to smem (overwrites halo; GEMM complete) ----
    #pragma unroll
    for (int i = 0; i < 4; ++i) {
        int p0 = (mgrp * 4 + i) * 16 + (lane >> 2);
        #pragma unroll
        for (int j = 0; j < 4; ++j) {
            if (j >= NTL) break;
            int t0 = (ngrp * 4 + j) * 8 + (lane & 3) * 2;
            if (t0 < WSQ) {
                float bb = attn_b[t0];
                logits_sh[p0 * 50 + t0]       = acc[i][j][0] + bb;
                logits_sh[(p0 + 8) * 50 + t0] = acc[i][j][2] + bb;
            }
            if (t0 + 1 < WSQ) {
                float bb = attn_b[t0 + 1];
                logits_sh[p0 * 50 + t0 + 1]       = acc[i][j][1] + bb;
                logits_sh[(p0 + 8) * 50 + t0 + 1] = acc[i][j][3] + bb;
            }
        }
    }
    __syncthreads();

    // ---- per-pixel softmax ----
    const int py = tid >> 5, px = tid & 31;
    float lg[WSQ];
    float mx = -1e30f;
    #pragma unroll
    for (int t = 0; t < WSQ; ++t) { lg[t] = logits_sh[tid * 50 + t]; mx = fmaxf(mx, lg[t]); }
    float sum = 0.0f;
    #pragma unroll
    for (int t = 0; t < WSQ; ++t) { lg[t] = __expf(lg[t] - mx); sum += lg[t]; }
    float inv = 1.0f / sum;
    #pragma unroll
    for (int t = 0; t < WSQ; ++t) lg[t] *= inv;

    const int b    = bh / HEADS;
    const int head = bh - b * HEADS;

    // ---- attn . V (8-channel chunks, channel-fastest smem) ----
    for (int vcblk = 0; vcblk < 4; ++vcblk) {
        __syncthreads();
        for (int idx = tid; idx < 8 * HALO_N; idx += 256) {
            int cc = idx / HALO_N;
            int rr = idx - cc * HALO_N;
            int hy = rr / 38, hx = rr - hy * 38;
            int gyy = ty0 - 3 + hy, gxx = tx0 - 3 + hx;
            float val = 0.0f;
            if ((unsigned)gyy < 128u && (unsigned)gxx < 128u)
                val = g_v[((((size_t)bh * 32) + vcblk * 8 + cc) << 14) + (gyy << 7) + gxx];
            v_sh[(hy * 40 + hx) * 8 + cc] = val;
        }
        __syncthreads();

        float o[8];
        #pragma unroll
        for (int vc = 0; vc < 8; ++vc) o[vc] = 0.0f;
        #pragma unroll
        for (int dy = 0; dy < 7; ++dy) {
            #pragma unroll
            for (int dx = 0; dx < 7; ++dx) {
                float a = lg[dy * 7 + dx];
                const float4* vp = (const float4*)&v_sh[((py + dy) * 40 + px + dx) * 8];
                float4 v0 = vp[0], v1 = vp[1];
                o[0] = fmaf(a, v0.x, o[0]); o[1] = fmaf(a, v0.y, o[1]);
                o[2] = fmaf(a, v0.z, o[2]); o[3] = fmaf(a, v0.w, o[3]);
                o[4] = fmaf(a, v1.x, o[4]); o[5] = fmaf(a, v1.y, o[5]);
                o[6] = fmaf(a, v1.z, o[6]); o[7] = fmaf(a, v1.w, o[7]);
            }
        }
        #pragma unroll
        for (int vc = 0; vc < 8; ++vc)
            g_att[((((size_t)b * DIMC) + head * 32 + vcblk * 8 + vc) << 14)
                  + ((ty0 + py) << 7) + (tx0 + px)] = o[vc];
    }
}

// ---------------- K3: 1x1 proj -> d_out ------------------------------------
__global__ __launch_bounds__(256, 2) void k3_proj(const float* __restrict__ w,
                                                  const float* __restrict__ bias,
                                                  float* __restrict__ out) {
    extern __shared__ float smem[];
    float* x_sh = smem;
    float* w_sh = smem + 96 * 128;
    const int tid = threadIdx.x;
    const int row = blockIdx.x;
    const int b   = blockIdx.y;
    const int m = tid & 31;
    const int n = tid >> 5;

    const float* xb = g_att + (((size_t)b * DIMC) << 14) + (row << 7);
    for (int idx = tid; idx < 96 * 128; idx += 256) {
        int c = idx >> 7, px = idx & 127;
        x_sh[idx] = xb[(((size_t)c) << 14) + px];
    }
    for (int idx = tid; idx < 96 * 96; idx += 256) w_sh[idx] = w[idx];
    __syncthreads();

    float acc[4][12];
    #pragma unroll
    for (int i = 0; i < 4; ++i)
        #pragma unroll
        for (int u = 0; u < 12; ++u) acc[i][u] = 0.0f;

    for (int k = 0; k < 96; ++k) {
        float4 a4 = *(const float4*)&x_sh[(k << 7) + m * 4];
        #pragma unroll
        for (int u = 0; u < 12; ++u) {
            float bw = w_sh[(n * 12 + u) * 96 + k];
            acc[0][u] = fmaf(a4.x, bw, acc[0][u]);
            acc[1][u] = fmaf(a4.y, bw, acc[1][u]);
            acc[2][u] = fmaf(a4.z, bw, acc[2][u]);
            acc[3][u] = fmaf(a4.w, bw, acc[3][u]);
        }
    }

    #pragma unroll
    for (int u = 0; u < 12; ++u) {
        int oc = n * 12 + u;
        float bs = bias[oc];
        float4 v4;
        v4.x = acc[0][u] + bs; v4.y = acc[1][u] + bs;
        v4.z = acc[2][u] + bs; v4.w = acc[3][u] + bs;
        *(float4*)(out + ((((size_t)b * DIMC) + oc) << 14) + (row << 7) + m * 4) = v4;
    }
}

// ---------------- launch ---------------------------------------------------
extern "C" void kernel_launch(void* const* d_in, const int* in_sizes, int n_in,
                              void* d_out, int out_size) {
    const float* x      = (const float*)d_in[0];
    const float* qkv_w  = (const float*)d_in[1];
    const float* qkv_b  = (const float*)d_in[2];
    const float* attn_w = (const float*)d_in[3];
    const float* attn_b = (const float*)d_in[4];
    const float* proj_w = (const float*)d_in[5];
    const float* proj_b = (const float*)d_in[6];
    float* out = (float*)d_out;

    const int SMEM_GEMM = (96 * 128 + 96 * 96) * 4;   // 86016 B

    cudaFuncSetAttribute(k1_qkv,  cudaFuncAttributeMaxDynamicSharedMemorySize, SMEM_GEMM);
    cudaFuncSetAttribute(k2_attn, cudaFuncAttributeMaxDynamicSharedMemorySize, SMEM_K2);
    cudaFuncSetAttribute(k3_proj, cudaFuncAttributeMaxDynamicSharedMemorySize, SMEM_GEMM);

    k0_prep<<<(WSQ * BTAPU2 + 255) / 256, 256>>>(attn_w);
    k1_qkv<<<dim3(128, BATCH), 256, SMEM_GEMM>>>(x, qkv_w, qkv_b);
    k2_attn<<<dim3(4, 16, NBH), 256, SMEM_K2>>>(attn_b);
    k3_proj<<<dim3(128, BATCH), 256, SMEM_GEMM>>>(proj_w, proj_b, out);
}

// round 8
// speedup vs baseline: 5.2256x; 1.3463x over previous
#include <cuda_runtime.h>
#include <cuda_fp16.h>
#include <cstdint>

#define BATCH 4
#define DIMC 96
#define HEADS 3
#define NBH 12
#define WSQ 49
#define QK_SCALE 0.17677669529663687f

// ---- k2 geometry ----
#define HPX 72
#define PXB 144
#define HALO_PX 532
#define HALO_BYTES (HALO_PX * PXB)   // 76608
#define BOFF2 HALO_BYTES
#define BTAPU2 896
#define SMEM_K2 (HALO_BYTES + 2 * BTAPU2 * 8)   // 90944
#define HALO_N 532

// ---- k1/k3 geometry ----
#define XPAD 132
#define SMEM_G (96 * XPAD * 4)       // 50688 B

#define NQKVF (36 * 12 * 32)         // 13824 qkv B fragments
#define NPROJF (12 * 12 * 32)        // 4608 proj B fragments

// ---------------- scratch (device globals) ----------------
__device__ __half g_qkh[(size_t)NBH * 128 * 128 * 64];   // [bh][y][x][64: q*s | k]
__device__ float  g_v  [(size_t)NBH * 32 * 128 * 128];   // [bh][32][y][x] planar
__device__ float  g_att[(size_t)BATCH * DIMC * 128 * 128];
__device__ uint2  g_w2f[(size_t)WSQ * BTAPU2];           // attn B frags (fp16)
__device__ uint2  g_wqkv[NQKVF];                         // qkv B frags (tf32)
__device__ uint2  g_wproj[NPROJF];                       // proj B frags (tf32)

__device__ __forceinline__ uint32_t tf32b(float x) {
    unsigned u;
    asm("cvt.rna.tf32.f32 %0, %1;" : "=r"(u) : "f"(x));
    return u;
}
__device__ __forceinline__ float to_tf32(float x) { return __uint_as_float(tf32b(x)); }

__device__ __forceinline__ void mma_tf32_16n8k8(float* acc, const uint32_t* a, uint2 b) {
    asm volatile(
        "mma.sync.aligned.m16n8k8.row.col.f32.tf32.tf32.f32 "
        "{%0,%1,%2,%3},{%4,%5,%6,%7},{%8,%9},{%0,%1,%2,%3};"
        : "+f"(acc[0]), "+f"(acc[1]), "+f"(acc[2]), "+f"(acc[3])
        : "r"(a[0]), "r"(a[1]), "r"(a[2]), "r"(a[3]), "r"(b.x), "r"(b.y));
}

// ---------------- K0: pack all weight fragments -----------------------------
__global__ void k0_prep(const float* __restrict__ attn_w,
                        const float* __restrict__ qkv_w,
                        const float* __restrict__ proj_w) {
    int idx = blockIdx.x * 256 + threadIdx.x;
    if (idx < WSQ * BTAPU2) {
        int lane = idx & 31;
        int nt   = (idx >> 5) % 7;
        int ks   = ((idx >> 5) / 7) & 3;
        int s    = idx / (32 * 28);
        int n = nt * 8 + (lane >> 2);
        int k0 = ks * 16 + (lane & 3) * 2;
        __half h[4];
        #pragma unroll
        for (int ii = 0; ii < 2; ++ii)
            h[ii] = (n < WSQ) ? __float2half(attn_w[(n * 64 + k0 + ii) * WSQ + s]) : __half(0.f);
        #pragma unroll
        for (int ii = 0; ii < 2; ++ii)
            h[2 + ii] = (n < WSQ) ? __float2half(attn_w[(n * 64 + k0 + 8 + ii) * WSQ + s]) : __half(0.f);
        uint2 u;
        u.x = *(const uint32_t*)&h[0];
        u.y = *(const uint32_t*)&h[2];
        g_w2f[idx] = u;
        return;
    }
    int i = idx - WSQ * BTAPU2;
    if (i < NQKVF) {
        int lane = i & 31, r = i >> 5;
        int ks = r % 12, nt = r / 12;
        int oc = nt * 8 + (lane >> 2);
        int k  = ks * 8 + (lane & 3);
        uint2 u;
        u.x = tf32b(qkv_w[oc * 96 + k]);
        u.y = tf32b(qkv_w[oc * 96 + k + 4]);
        g_wqkv[i] = u;
        return;
    }
    i -= NQKVF;
    if (i < NPROJF) {
        int lane = i & 31, r = i >> 5;
        int ks = r % 12, nt = r / 12;
        int oc = nt * 8 + (lane >> 2);
        int k  = ks * 8 + (lane & 3);
        uint2 u;
        u.x = tf32b(proj_w[oc * 96 + k]);
        u.y = tf32b(proj_w[oc * 96 + k + 4]);
        g_wproj[i] = u;
    }
}

// ---------------- K1: 1x1 qkv conv via tf32 mma -----------------------------
// block = (row y, batch b); 8 warps x 16 px mtiles. M=128 px, K=96, N=288.
__global__ __launch_bounds__(256, 2) void k1_qkv(const float* __restrict__ x,
                                                 const float* __restrict__ bias) {
    extern __shared__ float smem[];
    float* xs = smem;                               // [96][132] tf32
    const int tid = threadIdx.x, lane = tid & 31, wid = tid >> 5;
    const int row = blockIdx.x, b = blockIdx.y;

    const float4* xb = (const float4*)(x + (((size_t)b * DIMC) << 14) + (row << 7));
    #pragma unroll
    for (int it = 0; it < 12; ++it) {
        int idx = tid + it * 256;                   // 3072 float4
        int c = idx >> 5, p4 = idx & 31;
        float4 v = xb[(size_t)c * 4096 + p4];
        v.x = to_tf32(v.x); v.y = to_tf32(v.y); v.z = to_tf32(v.z); v.w = to_tf32(v.w);
        *(float4*)&xs[c * XPAD + p4 * 4] = v;
    }
    __syncthreads();

    const int px0 = wid * 16;
    const int pr = px0 + (lane >> 2);
    uint32_t A[12][4];
    #pragma unroll
    for (int ks = 0; ks < 12; ++ks) {
        int k0 = ks * 8 + (lane & 3);
        A[ks][0] = __float_as_uint(xs[k0 * XPAD + pr]);
        A[ks][1] = __float_as_uint(xs[k0 * XPAD + pr + 8]);
        A[ks][2] = __float_as_uint(xs[(k0 + 4) * XPAD + pr]);
        A[ks][3] = __float_as_uint(xs[(k0 + 4) * XPAD + pr + 8]);
    }

    const int bh_base = b * HEADS;
    for (int nt = 0; nt < 36; ++nt) {
        uint2 bf[12];
        #pragma unroll
        for (int ks = 0; ks < 12; ++ks) bf[ks] = g_wqkv[(nt * 12 + ks) * 32 + lane];
        float acc[4] = {0.f, 0.f, 0.f, 0.f};
        #pragma unroll
        for (int ks = 0; ks < 12; ++ks) mma_tf32_16n8k8(acc, A[ks], bf[ks]);

        int oc = nt * 8 + ((lane & 3) << 1);        // global oc in 0..287 (and oc+1)
        float b0 = bias[oc], b1 = bias[oc + 1];
        if (nt < 24) {                               // q (nt<12) or k
            int oc96 = oc - (nt < 12 ? 0 : 96);
            int head = oc96 >> 5, ch = (oc96 & 31) + (nt < 12 ? 0 : 32);
            size_t base = ((((size_t)(bh_base + head) * 128 + row) << 7));
            float s = (nt < 12) ? QK_SCALE : 1.0f;
            #pragma unroll
            for (int i = 0; i < 2; ++i) {
                int px = pr + i * 8;
                __half2 h = __floats2half2_rn((acc[2 * i] + b0) * s, (acc[2 * i + 1] + b1) * s);
                *(__half2*)&g_qkh[(base + px) * 64 + ch] = h;
            }
        } else {                                     // v -> planar fp32
            int oc96 = oc - 192;
            int head = oc96 >> 5, ch = oc96 & 31;
            float* vb = g_v + ((((size_t)(bh_base + head) * 32) + ch) << 14) + (row << 7);
            #pragma unroll
            for (int i = 0; i < 2; ++i) {
                int px = pr + i * 8;
                vb[px]           = acc[2 * i] + b0;
                vb[(1 << 14) + px] = acc[2 * i + 1] + b1;
            }
        }
    }
}

// ---------------- K2: fp16 mma logits conv + softmax + attn.V --------------
__global__ __launch_bounds__(256, 2) void k2_attn(const float* __restrict__ attn_b) {
    extern __shared__ char smemk2[];
    uint2* Bb = (uint2*)(smemk2 + BOFF2);
    float* logits_sh = (float*)smemk2;
    float* v_sh = (float*)(smemk2 + 256 * 50 * 4);

    const int tid = threadIdx.x;
    const int lane = tid & 31, wid = tid >> 5;
    const int mgrp = wid & 3, ngrp = wid >> 2;
    const int NTL = ngrp ? 3 : 4;
    const int bh  = blockIdx.z;
    const int ty0 = blockIdx.y * 8;
    const int tx0 = blockIdx.x * 32;

    uint32_t sb;
    { uint64_t t_; asm("cvta.to.shared.u64 %0, %1;" : "=l"(t_) : "l"(smemk2)); sb = (uint32_t)t_; }

    const uint4* qk4 = (const uint4*)g_qkh;
    for (int idx = tid; idx < HALO_PX * 8; idx += 256) {
        int pxi = idx >> 3, g = idx & 7;
        int hy = pxi / 38, hx = pxi - hy * 38;
        int gy = ty0 - 3 + hy, gx = tx0 - 3 + hx;
        uint4 val = make_uint4(0, 0, 0, 0);
        if ((unsigned)gy < 128u && (unsigned)gx < 128u)
            val = qk4[((((size_t)bh * 128 + gy) << 7) + gx) * 8 + g];
        *(uint4*)(smemk2 + pxi * PXB + g * 16) = val;
    }
    for (int i = tid; i < BTAPU2; i += 256) Bb[i] = g_w2f[i];
    __syncthreads();

    const int mrow = lane & 15;
    const int khalf = lane >> 4;
    uint32_t abase[4];
    #pragma unroll
    for (int i = 0; i < 4; ++i) {
        int p = (mgrp * 4 + i) * 16 + mrow;
        abase[i] = sb + ((p >> 5) * 38 + (p & 31)) * PXB + khalf * 16;
    }

    float acc[4][4][4];
    #pragma unroll
    for (int i = 0; i < 4; ++i)
        #pragma unroll
        for (int j = 0; j < 4; ++j)
            #pragma unroll
            for (int e = 0; e < 4; ++e) acc[i][j][e] = 0.0f;

    for (int s = 0; s < WSQ; ++s) {
        uint2 tb[4];
        if (s < WSQ - 1) {
            #pragma unroll
            for (int u = 0; u < 4; ++u) {
                int i2 = tid + u * 256;
                if (i2 < BTAPU2) tb[u] = g_w2f[(size_t)(s + 1) * BTAPU2 + i2];
            }
        }
        const uint2* cur = Bb + (s & 1) * BTAPU2;
        int dy = s / 7, dx = s - dy * 7;
        uint32_t toff = (uint32_t)(dy * 38 + dx) * PXB;

        #pragma unroll
        for (int ks = 0; ks < 4; ++ks) {
            uint32_t a[4][4];
            #pragma unroll
            for (int i = 0; i < 4; ++i) {
                asm volatile("ldmatrix.sync.aligned.m8n8.x4.shared.b16 {%0,%1,%2,%3}, [%4];"
                    : "=r"(a[i][0]), "=r"(a[i][1]), "=r"(a[i][2]), "=r"(a[i][3])
                    : "r"(abase[i] + toff + ks * 32));
            }
            uint2 bf[4];
            #pragma unroll
            for (int j = 0; j < 4; ++j) {
                if (j >= NTL) break;
                bf[j] = cur[(ks * 7 + ngrp * 4 + j) * 32 + lane];
            }
            #pragma unroll
            for (int j = 0; j < 4; ++j) {
                if (j >= NTL) break;
                #pragma unroll
                for (int i = 0; i < 4; ++i) {
                    asm volatile(
                        "mma.sync.aligned.m16n8k16.row.col.f32.f16.f16.f32 "
                        "{%0,%1,%2,%3},{%4,%5,%6,%7},{%8,%9},{%0,%1,%2,%3};"
                        : "+f"(acc[i][j][0]), "+f"(acc[i][j][1]),
                          "+f"(acc[i][j][2]), "+f"(acc[i][j][3])
                        : "r"(a[i][0]), "r"(a[i][1]), "r"(a[i][2]), "r"(a[i][3]),
                          "r"(bf[j].x), "r"(bf[j].y));
                }
            }
        }
        if (s < WSQ - 1) {
            #pragma unroll
            for (int u = 0; u < 4; ++u) {
                int i2 = tid + u * 256;
                if (i2 < BTAPU2) Bb[((s + 1) & 1) * BTAPU2 + i2] = tb[u];
            }
        }
        __syncthreads();
    }

    #pragma unroll
    for (int i = 0; i < 4; ++i) {
        int p0 = (mgrp * 4 + i) * 16 + (lane >> 2);
        #pragma unroll
        for (int j = 0; j < 4; ++j) {
            if (j >= NTL) break;
            int t0 = (ngrp * 4 + j) * 8 + (lane & 3) * 2;
            if (t0 < WSQ) {
                float bb = attn_b[t0];
                logits_sh[p0 * 50 + t0]       = acc[i][j][0] + bb;
                logits_sh[(p0 + 8) * 50 + t0] = acc[i][j][2] + bb;
            }
            if (t0 + 1 < WSQ) {
                float bb = attn_b[t0 + 1];
                logits_sh[p0 * 50 + t0 + 1]       = acc[i][j][1] + bb;
                logits_sh[(p0 + 8) * 50 + t0 + 1] = acc[i][j][3] + bb;
            }
        }
    }
    __syncthreads();

    const int py = tid >> 5, px = tid & 31;
    float lg[WSQ];
    float mx = -1e30f;
    #pragma unroll
    for (int t = 0; t < WSQ; ++t) { lg[t] = logits_sh[tid * 50 + t]; mx = fmaxf(mx, lg[t]); }
    float sum = 0.0f;
    #pragma unroll
    for (int t = 0; t < WSQ; ++t) { lg[t] = __expf(lg[t] - mx); sum += lg[t]; }
    float inv = 1.0f / sum;
    #pragma unroll
    for (int t = 0; t < WSQ; ++t) lg[t] *= inv;

    const int b    = bh / HEADS;
    const int head = bh - b * HEADS;

    for (int vcblk = 0; vcblk < 4; ++vcblk) {
        __syncthreads();
        for (int idx = tid; idx < 8 * HALO_N; idx += 256) {
            int cc = idx / HALO_N;
            int rr = idx - cc * HALO_N;
            int hy = rr / 38, hx = rr - hy * 38;
            int gyy = ty0 - 3 + hy, gxx = tx0 - 3 + hx;
            float val = 0.0f;
            if ((unsigned)gyy < 128u && (unsigned)gxx < 128u)
                val = g_v[((((size_t)bh * 32) + vcblk * 8 + cc) << 14) + (gyy << 7) + gxx];
            v_sh[(hy * 40 + hx) * 8 + cc] = val;
        }
        __syncthreads();

        float o[8];
        #pragma unroll
        for (int vc = 0; vc < 8; ++vc) o[vc] = 0.0f;
        #pragma unroll
        for (int dy = 0; dy < 7; ++dy) {
            #pragma unroll
            for (int dx = 0; dx < 7; ++dx) {
                float a = lg[dy * 7 + dx];
                const float4* vp = (const float4*)&v_sh[((py + dy) * 40 + px + dx) * 8];
                float4 v0 = vp[0], v1 = vp[1];
                o[0] = fmaf(a, v0.x, o[0]); o[1] = fmaf(a, v0.y, o[1]);
                o[2] = fmaf(a, v0.z, o[2]); o[3] = fmaf(a, v0.w, o[3]);
                o[4] = fmaf(a, v1.x, o[4]); o[5] = fmaf(a, v1.y, o[5]);
                o[6] = fmaf(a, v1.z, o[6]); o[7] = fmaf(a, v1.w, o[7]);
            }
        }
        #pragma unroll
        for (int vc = 0; vc < 8; ++vc)
            g_att[((((size_t)b * DIMC) + head * 32 + vcblk * 8 + vc) << 14)
                  + ((ty0 + py) << 7) + (tx0 + px)] = o[vc];
    }
}

// ---------------- K3: 1x1 proj via tf32 mma -> d_out ------------------------
__global__ __launch_bounds__(256, 2) void k3_proj(const float* __restrict__ bias,
                                                  float* __restrict__ out) {
    extern __shared__ float smem[];
    float* xs = smem;                               // [96][132] tf32
    const int tid = threadIdx.x, lane = tid & 31, wid = tid >> 5;
    const int row = blockIdx.x, b = blockIdx.y;

    const float4* xb = (const float4*)(g_att + (((size_t)b * DIMC) << 14) + (row << 7));
    #pragma unroll
    for (int it = 0; it < 12; ++it) {
        int idx = tid + it * 256;
        int c = idx >> 5, p4 = idx & 31;
        float4 v = xb[(size_t)c * 4096 + p4];
        v.x = to_tf32(v.x); v.y = to_tf32(v.y); v.z = to_tf32(v.z); v.w = to_tf32(v.w);
        *(float4*)&xs[c * XPAD + p4 * 4] = v;
    }
    __syncthreads();

    const int px0 = wid * 16;
    const int pr = px0 + (lane >> 2);
    uint32_t A[12][4];
    #pragma unroll
    for (int ks = 0; ks < 12; ++ks) {
        int k0 = ks * 8 + (lane & 3);
        A[ks][0] = __float_as_uint(xs[k0 * XPAD + pr]);
        A[ks][1] = __float_as_uint(xs[k0 * XPAD + pr + 8]);
        A[ks][2] = __float_as_uint(xs[(k0 + 4) * XPAD + pr]);
        A[ks][3] = __float_as_uint(xs[(k0 + 4) * XPAD + pr + 8]);
    }

    for (int nt = 0; nt < 12; ++nt) {
        uint2 bf[12];
        #pragma unroll
        for (int ks = 0; ks < 12; ++ks) bf[ks] = g_wproj[(nt * 12 + ks) * 32 + lane];
        float acc[4] = {0.f, 0.f, 0.f, 0.f};
        #pragma unroll
        for (int ks = 0; ks < 12; ++ks) mma_tf32_16n8k8(acc, A[ks], bf[ks]);

        int oc = nt * 8 + ((lane & 3) << 1);
        float b0 = bias[oc], b1 = bias[oc + 1];
        float* ob = out + ((((size_t)b * DIMC) + oc) << 14) + (row << 7);
        #pragma unroll
        for (int i = 0; i < 2; ++i) {
            int px = pr + i * 8;
            ob[px]            = acc[2 * i] + b0;
            ob[(1 << 14) + px] = acc[2 * i + 1] + b1;
        }
    }
}

// ---------------- launch ---------------------------------------------------
extern "C" void kernel_launch(void* const* d_in, const int* in_sizes, int n_in,
                              void* d_out, int out_size) {
    const float* x      = (const float*)d_in[0];
    const float* qkv_w  = (const float*)d_in[1];
    const float* qkv_b  = (const float*)d_in[2];
    const float* attn_w = (const float*)d_in[3];
    const float* attn_b = (const float*)d_in[4];
    const float* proj_w = (const float*)d_in[5];
    const float* proj_b = (const float*)d_in[6];
    float* out = (float*)d_out;

    cudaFuncSetAttribute(k1_qkv,  cudaFuncAttributeMaxDynamicSharedMemorySize, SMEM_G);
    cudaFuncSetAttribute(k2_attn, cudaFuncAttributeMaxDynamicSharedMemorySize, SMEM_K2);
    cudaFuncSetAttribute(k3_proj, cudaFuncAttributeMaxDynamicSharedMemorySize, SMEM_G);

    const int k0n = WSQ * BTAPU2 + NQKVF + NPROJF;
    k0_prep<<<(k0n + 255) / 256, 256>>>(attn_w, qkv_w, proj_w);
    k1_qkv<<<dim3(128, BATCH), 256, SMEM_G>>>(x, qkv_b);
    k2_attn<<<dim3(4, 16, NBH), 256, SMEM_K2>>>(attn_b);
    k3_proj<<<dim3(128, BATCH), 256, SMEM_G>>>(proj_b, out);
}

// round 9
// speedup vs baseline: 5.4661x; 1.0460x over previous
#include <cuda_runtime.h>
#include <cuda_fp16.h>
#include <cstdint>

#define BATCH 4
#define DIMC 96
#define HEADS 3
#define NBH 12
#define WSQ 49
#define QK_SCALE 0.17677669529663687f

// ---- k2 geometry ----
#define PXB 144
#define HALO_PX 532
#define HALO_BYTES (HALO_PX * PXB)   // 76608
#define BOFF2 HALO_BYTES
#define BTAPU2 896                   // uint2 per tap: 4 ks * 7 nt * 32 lanes
#define BSLOT (BTAPU2 * 8)           // 7168 B
#define SMEM_K2 (HALO_BYTES + 4 * BSLOT)   // 105280
#define HALO_N 532

// ---- k1/k3 geometry ----
#define XPAD 132
#define SMEM_G (96 * XPAD * 4)       // 50688 B
#define NQKVF (36 * 12 * 32)
#define NPROJF (12 * 12 * 32)

// ---------------- scratch (device globals) ----------------
__device__ __half g_qkh[(size_t)NBH * 128 * 128 * 64];
__device__ float  g_v  [(size_t)NBH * 32 * 128 * 128];
__device__ float  g_att[(size_t)BATCH * DIMC * 128 * 128];
__device__ uint2  g_w2f[(size_t)WSQ * BTAPU2];
__device__ uint2  g_wqkv[NQKVF];
__device__ uint2  g_wproj[NPROJF];

__device__ __forceinline__ uint32_t tf32b(float x) {
    unsigned u;
    asm("cvt.rna.tf32.f32 %0, %1;" : "=r"(u) : "f"(x));
    return u;
}
__device__ __forceinline__ float to_tf32(float x) { return __uint_as_float(tf32b(x)); }

__device__ __forceinline__ void mma_tf32_16n8k8(float* acc, const uint32_t* a, uint2 b) {
    asm volatile(
        "mma.sync.aligned.m16n8k8.row.col.f32.tf32.tf32.f32 "
        "{%0,%1,%2,%3},{%4,%5,%6,%7},{%8,%9},{%0,%1,%2,%3};"
        : "+f"(acc[0]), "+f"(acc[1]), "+f"(acc[2]), "+f"(acc[3])
        : "r"(a[0]), "r"(a[1]), "r"(a[2]), "r"(a[3]), "r"(b.x), "r"(b.y));
}
__device__ __forceinline__ void mma_f16_16n8k16(float* acc, const uint32_t* a, uint2 b) {
    asm volatile(
        "mma.sync.aligned.m16n8k16.row.col.f32.f16.f16.f32 "
        "{%0,%1,%2,%3},{%4,%5,%6,%7},{%8,%9},{%0,%1,%2,%3};"
        : "+f"(acc[0]), "+f"(acc[1]), "+f"(acc[2]), "+f"(acc[3])
        : "r"(a[0]), "r"(a[1]), "r"(a[2]), "r"(a[3]), "r"(b.x), "r"(b.y));
}

// ---------------- K0: pack all weight fragments -----------------------------
__global__ void k0_prep(const float* __restrict__ attn_w,
                        const float* __restrict__ qkv_w,
                        const float* __restrict__ proj_w) {
    int idx = blockIdx.x * 256 + threadIdx.x;
    if (idx < WSQ * BTAPU2) {
        int lane = idx & 31;
        int nt   = (idx >> 5) % 7;
        int ks   = ((idx >> 5) / 7) & 3;
        int s    = idx / (32 * 28);
        int n = nt * 8 + (lane >> 2);
        int k0 = ks * 16 + (lane & 3) * 2;
        __half h[4];
        #pragma unroll
        for (int ii = 0; ii < 2; ++ii)
            h[ii] = (n < WSQ) ? __float2half(attn_w[(n * 64 + k0 + ii) * WSQ + s]) : __half(0.f);
        #pragma unroll
        for (int ii = 0; ii < 2; ++ii)
            h[2 + ii] = (n < WSQ) ? __float2half(attn_w[(n * 64 + k0 + 8 + ii) * WSQ + s]) : __half(0.f);
        uint2 u;
        u.x = *(const uint32_t*)&h[0];
        u.y = *(const uint32_t*)&h[2];
        g_w2f[idx] = u;
        return;
    }
    int i = idx - WSQ * BTAPU2;
    if (i < NQKVF) {
        int lane = i & 31, r = i >> 5;
        int ks = r % 12, nt = r / 12;
        int oc = nt * 8 + (lane >> 2);
        int k  = ks * 8 + (lane & 3);
        uint2 u;
        u.x = tf32b(qkv_w[oc * 96 + k]);
        u.y = tf32b(qkv_w[oc * 96 + k + 4]);
        g_wqkv[i] = u;
        return;
    }
    i -= NQKVF;
    if (i < NPROJF) {
        int lane = i & 31, r = i >> 5;
        int ks = r % 12, nt = r / 12;
        int oc = nt * 8 + (lane >> 2);
        int k  = ks * 8 + (lane & 3);
        uint2 u;
        u.x = tf32b(proj_w[oc * 96 + k]);
        u.y = tf32b(proj_w[oc * 96 + k + 4]);
        g_wproj[i] = u;
    }
}

// ---------------- K1: 1x1 qkv conv via tf32 mma -----------------------------
__global__ __launch_bounds__(256, 2) void k1_qkv(const float* __restrict__ x,
                                                 const float* __restrict__ bias) {
    extern __shared__ float smem[];
    float* xs = smem;
    const int tid = threadIdx.x, lane = tid & 31, wid = tid >> 5;
    const int row = blockIdx.x, b = blockIdx.y;

    const float4* xb = (const float4*)(x + (((size_t)b * DIMC) << 14) + (row << 7));
    #pragma unroll
    for (int it = 0; it < 12; ++it) {
        int idx = tid + it * 256;
        int c = idx >> 5, p4 = idx & 31;
        float4 v = xb[(size_t)c * 4096 + p4];
        v.x = to_tf32(v.x); v.y = to_tf32(v.y); v.z = to_tf32(v.z); v.w = to_tf32(v.w);
        *(float4*)&xs[c * XPAD + p4 * 4] = v;
    }
    __syncthreads();

    const int pr = wid * 16 + (lane >> 2);
    uint32_t A[12][4];
    #pragma unroll
    for (int ks = 0; ks < 12; ++ks) {
        int k0 = ks * 8 + (lane & 3);
        A[ks][0] = __float_as_uint(xs[k0 * XPAD + pr]);
        A[ks][1] = __float_as_uint(xs[k0 * XPAD + pr + 8]);
        A[ks][2] = __float_as_uint(xs[(k0 + 4) * XPAD + pr]);
        A[ks][3] = __float_as_uint(xs[(k0 + 4) * XPAD + pr + 8]);
    }

    const int bh_base = b * HEADS;
    for (int nt = 0; nt < 36; ++nt) {
        uint2 bf[12];
        #pragma unroll
        for (int ks = 0; ks < 12; ++ks) bf[ks] = g_wqkv[(nt * 12 + ks) * 32 + lane];
        float acc[4] = {0.f, 0.f, 0.f, 0.f};
        #pragma unroll
        for (int ks = 0; ks < 12; ++ks) mma_tf32_16n8k8(acc, A[ks], bf[ks]);

        int oc = nt * 8 + ((lane & 3) << 1);
        float b0 = bias[oc], b1 = bias[oc + 1];
        if (nt < 24) {
            int oc96 = oc - (nt < 12 ? 0 : 96);
            int head = oc96 >> 5, ch = (oc96 & 31) + (nt < 12 ? 0 : 32);
            size_t base = ((((size_t)(bh_base + head) * 128 + row) << 7));
            float s = (nt < 12) ? QK_SCALE : 1.0f;
            #pragma unroll
            for (int i = 0; i < 2; ++i) {
                int px = pr + i * 8;
                __half2 h = __floats2half2_rn((acc[2 * i] + b0) * s, (acc[2 * i + 1] + b1) * s);
                *(__half2*)&g_qkh[(base + px) * 64 + ch] = h;
            }
        } else {
            int oc96 = oc - 192;
            int head = oc96 >> 5, ch = oc96 & 31;
            float* vb = g_v + ((((size_t)(bh_base + head) * 32) + ch) << 14) + (row << 7);
            #pragma unroll
            for (int i = 0; i < 2; ++i) {
                int px = pr + i * 8;
                vb[px]             = acc[2 * i] + b0;
                vb[(1 << 14) + px] = acc[2 * i + 1] + b1;
            }
        }
    }
}

// ---------------- K2: fp16 mma logits conv + softmax + attn.V --------------
// 8 warps; warp w owns mtiles {2w,2w+1} (32 px) x ALL 7 ntiles. Uniform unroll.
// B: 4-slot ring, 2 taps per iter, sync every 2 taps.
__global__ __launch_bounds__(256, 2) void k2_attn(const float* __restrict__ attn_b) {
    extern __shared__ char smemk2[];
    uint2* Bring = (uint2*)(smemk2 + BOFF2);         // 4 slots x 896 uint2
    float* logits_sh = (float*)smemk2;
    float* v_sh = (float*)(smemk2 + 256 * 50 * 4);

    const int tid = threadIdx.x;
    const int lane = tid & 31, wid = tid >> 5;
    const int bh  = blockIdx.z;
    const int ty0 = blockIdx.y * 8;
    const int tx0 = blockIdx.x * 32;

    uint32_t sb;
    { uint64_t t_; asm("cvta.to.shared.u64 %0, %1;" : "=l"(t_) : "l"(smemk2)); sb = (uint32_t)t_; }

    // ---- load qk halo ----
    const uint4* qk4 = (const uint4*)g_qkh;
    for (int idx = tid; idx < HALO_PX * 8; idx += 256) {
        int pxi = idx >> 3, g = idx & 7;
        int hy = pxi / 38, hx = pxi - hy * 38;
        int gy = ty0 - 3 + hy, gx = tx0 - 3 + hx;
        uint4 val = make_uint4(0, 0, 0, 0);
        if ((unsigned)gy < 128u && (unsigned)gx < 128u)
            val = qk4[((((size_t)bh * 128 + gy) << 7) + gx) * 8 + g];
        *(uint4*)(smemk2 + pxi * PXB + g * 16) = val;
    }
    // prologue: taps 0,1 -> slots 0,1
    for (int i = tid; i < 2 * BTAPU2; i += 256) Bring[i] = g_w2f[i];
    __syncthreads();

    // ldmatrix bases: warp w -> mtiles 2w, 2w+1
    uint32_t abase[2];
    #pragma unroll
    for (int m = 0; m < 2; ++m) {
        int p = (2 * wid + m) * 16 + (lane & 15);
        abase[m] = sb + ((p >> 5) * 38 + (p & 31)) * PXB + (lane >> 4) * 16;
    }

    float acc[2][7][4];
    #pragma unroll
    for (int m = 0; m < 2; ++m)
        #pragma unroll
        for (int nt = 0; nt < 7; ++nt)
            #pragma unroll
            for (int e = 0; e < 4; ++e) acc[m][nt][e] = 0.0f;

    for (int s = 0; s < WSQ; s += 2) {
        // prefetch taps s+2, s+3 into registers
        uint2 tb[8];
        const bool h2 = (s + 2) < WSQ, h3 = (s + 3) < WSQ;
        #pragma unroll
        for (int u = 0; u < 4; ++u) {
            int i2 = tid + u * 256;
            if (h2 && i2 < BTAPU2) tb[u]     = g_w2f[(size_t)(s + 2) * BTAPU2 + i2];
            if (h3 && i2 < BTAPU2) tb[4 + u] = g_w2f[(size_t)(s + 3) * BTAPU2 + i2];
        }

        // 2 taps of mma
        #pragma unroll
        for (int q = 0; q < 2; ++q) {
            int sq = s + q;
            if (q == 1 && sq >= WSQ) break;
            const uint2* cur = Bring + (sq & 3) * BTAPU2;
            int dy = sq / 7, dx = sq - dy * 7;
            uint32_t toff = (uint32_t)(dy * 38 + dx) * PXB;
            #pragma unroll
            for (int ks = 0; ks < 4; ++ks) {
                uint32_t a[2][4];
                #pragma unroll
                for (int m = 0; m < 2; ++m) {
                    asm volatile("ldmatrix.sync.aligned.m8n8.x4.shared.b16 {%0,%1,%2,%3}, [%4];"
                        : "=r"(a[m][0]), "=r"(a[m][1]), "=r"(a[m][2]), "=r"(a[m][3])
                        : "r"(abase[m] + toff + ks * 32));
                }
                uint2 bf[7];
                #pragma unroll
                for (int nt = 0; nt < 7; ++nt) bf[nt] = cur[(ks * 7 + nt) * 32 + lane];
                #pragma unroll
                for (int nt = 0; nt < 7; ++nt) {
                    mma_f16_16n8k16(acc[0][nt], a[0], bf[nt]);
                    mma_f16_16n8k16(acc[1][nt], a[1], bf[nt]);
                }
            }
        }

        // store prefetched taps into ring slots (s+2)&3, (s+3)&3
        #pragma unroll
        for (int u = 0; u < 4; ++u) {
            int i2 = tid + u * 256;
            if (h2 && i2 < BTAPU2) Bring[((s + 2) & 3) * BTAPU2 + i2] = tb[u];
            if (h3 && i2 < BTAPU2) Bring[((s + 3) & 3) * BTAPU2 + i2] = tb[4 + u];
        }
        __syncthreads();
    }

    // ---- logits (+bias) to smem ----
    #pragma unroll
    for (int m = 0; m < 2; ++m) {
        int p0 = (2 * wid + m) * 16 + (lane >> 2);
        #pragma unroll
        for (int nt = 0; nt < 7; ++nt) {
            int t0 = nt * 8 + (lane & 3) * 2;
            if (t0 < WSQ) {
                float bb = attn_b[t0];
                logits_sh[p0 * 50 + t0]       = acc[m][nt][0] + bb;
                logits_sh[(p0 + 8) * 50 + t0] = acc[m][nt][2] + bb;
            }
            if (t0 + 1 < WSQ) {
                float bb = attn_b[t0 + 1];
                logits_sh[p0 * 50 + t0 + 1]       = acc[m][nt][1] + bb;
                logits_sh[(p0 + 8) * 50 + t0 + 1] = acc[m][nt][3] + bb;
            }
        }
    }
    __syncthreads();

    // ---- per-pixel softmax ----
    const int py = tid >> 5, px = tid & 31;
    float lg[WSQ];
    float mx = -1e30f;
    #pragma unroll
    for (int t = 0; t < WSQ; ++t) { lg[t] = logits_sh[tid * 50 + t]; mx = fmaxf(mx, lg[t]); }
    float sum = 0.0f;
    #pragma unroll
    for (int t = 0; t < WSQ; ++t) { lg[t] = __expf(lg[t] - mx); sum += lg[t]; }
    float inv = 1.0f / sum;
    #pragma unroll
    for (int t = 0; t < WSQ; ++t) lg[t] *= inv;

    const int b    = bh / HEADS;
    const int head = bh - b * HEADS;

    // ---- attn . V ----
    for (int vcblk = 0; vcblk < 4; ++vcblk) {
        __syncthreads();
        for (int idx = tid; idx < 8 * HALO_N; idx += 256) {
            int cc = idx / HALO_N;
            int rr = idx - cc * HALO_N;
            int hy = rr / 38, hx = rr - hy * 38;
            int gyy = ty0 - 3 + hy, gxx = tx0 - 3 + hx;
            float val = 0.0f;
            if ((unsigned)gyy < 128u && (unsigned)gxx < 128u)
                val = g_v[((((size_t)bh * 32) + vcblk * 8 + cc) << 14) + (gyy << 7) + gxx];
            v_sh[(hy * 40 + hx) * 8 + cc] = val;
        }
        __syncthreads();

        float o[8];
        #pragma unroll
        for (int vc = 0; vc < 8; ++vc) o[vc] = 0.0f;
        #pragma unroll
        for (int dy = 0; dy < 7; ++dy) {
            #pragma unroll
            for (int dx = 0; dx < 7; ++dx) {
                float a = lg[dy * 7 + dx];
                const float4* vp = (const float4*)&v_sh[((py + dy) * 40 + px + dx) * 8];
                float4 v0 = vp[0], v1 = vp[1];
                o[0] = fmaf(a, v0.x, o[0]); o[1] = fmaf(a, v0.y, o[1]);
                o[2] = fmaf(a, v0.z, o[2]); o[3] = fmaf(a, v0.w, o[3]);
                o[4] = fmaf(a, v1.x, o[4]); o[5] = fmaf(a, v1.y, o[5]);
                o[6] = fmaf(a, v1.z, o[6]); o[7] = fmaf(a, v1.w, o[7]);
            }
        }
        #pragma unroll
        for (int vc = 0; vc < 8; ++vc)
            g_att[((((size_t)b * DIMC) + head * 32 + vcblk * 8 + vc) << 14)
                  + ((ty0 + py) << 7) + (tx0 + px)] = o[vc];
    }
}

// ---------------- K3: 1x1 proj via tf32 mma -> d_out ------------------------
__global__ __launch_bounds__(256, 2) void k3_proj(const float* __restrict__ bias,
                                                  float* __restrict__ out) {
    extern __shared__ float smem[];
    float* xs = smem;
    const int tid = threadIdx.x, lane = tid & 31, wid = tid >> 5;
    const int row = blockIdx.x, b = blockIdx.y;

    const float4* xb = (const float4*)(g_att + (((size_t)b * DIMC) << 14) + (row << 7));
    #pragma unroll
    for (int it = 0; it < 12; ++it) {
        int idx = tid + it * 256;
        int c = idx >> 5, p4 = idx & 31;
        float4 v = xb[(size_t)c * 4096 + p4];
        v.x = to_tf32(v.x); v.y = to_tf32(v.y); v.z = to_tf32(v.z); v.w = to_tf32(v.w);
        *(float4*)&xs[c * XPAD + p4 * 4] = v;
    }
    __syncthreads();

    const int pr = wid * 16 + (lane >> 2);
    uint32_t A[12][4];
    #pragma unroll
    for (int ks = 0; ks < 12; ++ks) {
        int k0 = ks * 8 + (lane & 3);
        A[ks][0] = __float_as_uint(xs[k0 * XPAD + pr]);
        A[ks][1] = __float_as_uint(xs[k0 * XPAD + pr + 8]);
        A[ks][2] = __float_as_uint(xs[(k0 + 4) * XPAD + pr]);
        A[ks][3] = __float_as_uint(xs[(k0 + 4) * XPAD + pr + 8]);
    }

    for (int nt = 0; nt < 12; ++nt) {
        uint2 bf[12];
        #pragma unroll
        for (int ks = 0; ks < 12; ++ks) bf[ks] = g_wproj[(nt * 12 + ks) * 32 + lane];
        float acc[4] = {0.f, 0.f, 0.f, 0.f};
        #pragma unroll
        for (int ks = 0; ks < 12; ++ks) mma_tf32_16n8k8(acc, A[ks], bf[ks]);

        int oc = nt * 8 + ((lane & 3) << 1);
        float b0 = bias[oc], b1 = bias[oc + 1];
        float* ob = out + ((((size_t)b * DIMC) + oc) << 14) + (row << 7);
        #pragma unroll
        for (int i = 0; i < 2; ++i) {
            int px = pr + i * 8;
            ob[px]             = acc[2 * i] + b0;
            ob[(1 << 14) + px] = acc[2 * i + 1] + b1;
        }
    }
}

// ---------------- launch ---------------------------------------------------
extern "C" void kernel_launch(void* const* d_in, const int* in_sizes, int n_in,
                              void* d_out, int out_size) {
    const float* x      = (const float*)d_in[0];
    const float* qkv_w  = (const float*)d_in[1];
    const float* qkv_b  = (const float*)d_in[2];
    const float* attn_w = (const float*)d_in[3];
    const float* attn_b = (const float*)d_in[4];
    const float* proj_w = (const float*)d_in[5];
    const float* proj_b = (const float*)d_in[6];
    float* out = (float*)d_out;

    cudaFuncSetAttribute(k1_qkv,  cudaFuncAttributeMaxDynamicSharedMemorySize, SMEM_G);
    cudaFuncSetAttribute(k2_attn, cudaFuncAttributeMaxDynamicSharedMemorySize, SMEM_K2);
    cudaFuncSetAttribute(k3_proj, cudaFuncAttributeMaxDynamicSharedMemorySize, SMEM_G);

    const int k0n = WSQ * BTAPU2 + NQKVF + NPROJF;
    k0_prep<<<(k0n + 255) / 256, 256>>>(attn_w, qkv_w, proj_w);
    k1_qkv<<<dim3(128, BATCH), 256, SMEM_G>>>(x, qkv_b);
    k2_attn<<<dim3(4, 16, NBH), 256, SMEM_K2>>>(attn_b);
    k3_proj<<<dim3(128, BATCH), 256, SMEM_G>>>(proj_b, out);
}

// round 10
// speedup vs baseline: 5.6572x; 1.0350x over previous
#include <cuda_runtime.h>
#include <cuda_fp16.h>
#include <cstdint>

#define BATCH 4
#define DIMC 96
#define HEADS 3
#define NBH 12
#define WSQ 49
#define QK_SCALE 0.17677669529663687f

// ---- k2 geometry ----
#define PXB 144
#define HALO_PX 532
#define HALO_BYTES (HALO_PX * PXB)   // 76608
#define BTAPU2 896                   // uint2 per tap: 4 ks * 7 nt * 32 lanes
#define SMEM_K2 HALO_BYTES           // 76608 (epilogue needs 69120, fits)
#define HALO_N 532

// ---- k1/k3 geometry ----
#define XPAD 132
#define SMEM_G (96 * XPAD * 4)       // 50688 B
#define NQKVF (36 * 12 * 32)
#define NPROJF (12 * 12 * 32)

// ---------------- scratch (device globals) ----------------
__device__ __half g_qkh[(size_t)NBH * 128 * 128 * 64];
__device__ float  g_v  [(size_t)NBH * 32 * 128 * 128];
__device__ float  g_att[(size_t)BATCH * DIMC * 128 * 128];
__device__ uint2  g_w2f[(size_t)WSQ * BTAPU2];
__device__ uint2  g_wqkv[NQKVF];
__device__ uint2  g_wproj[NPROJF];

__device__ __forceinline__ uint32_t tf32b(float x) {
    unsigned u;
    asm("cvt.rna.tf32.f32 %0, %1;" : "=r"(u) : "f"(x));
    return u;
}
__device__ __forceinline__ float to_tf32(float x) { return __uint_as_float(tf32b(x)); }

__device__ __forceinline__ void mma_tf32_16n8k8(float* acc, const uint32_t* a, uint2 b) {
    asm volatile(
        "mma.sync.aligned.m16n8k8.row.col.f32.tf32.tf32.f32 "
        "{%0,%1,%2,%3},{%4,%5,%6,%7},{%8,%9},{%0,%1,%2,%3};"
        : "+f"(acc[0]), "+f"(acc[1]), "+f"(acc[2]), "+f"(acc[3])
        : "r"(a[0]), "r"(a[1]), "r"(a[2]), "r"(a[3]), "r"(b.x), "r"(b.y));
}
__device__ __forceinline__ void mma_f16_16n8k16(float* acc, const uint32_t* a, uint2 b) {
    asm volatile(
        "mma.sync.aligned.m16n8k16.row.col.f32.f16.f16.f32 "
        "{%0,%1,%2,%3},{%4,%5,%6,%7},{%8,%9},{%0,%1,%2,%3};"
        : "+f"(acc[0]), "+f"(acc[1]), "+f"(acc[2]), "+f"(acc[3])
        : "r"(a[0]), "r"(a[1]), "r"(a[2]), "r"(a[3]), "r"(b.x), "r"(b.y));
}

// ---------------- K0: pack all weight fragments -----------------------------
__global__ void k0_prep(const float* __restrict__ attn_w,
                        const float* __restrict__ qkv_w,
                        const float* __restrict__ proj_w) {
    int idx = blockIdx.x * 256 + threadIdx.x;
    if (idx < WSQ * BTAPU2) {
        int lane = idx & 31;
        int nt   = (idx >> 5) % 7;
        int ks   = ((idx >> 5) / 7) & 3;
        int s    = idx / (32 * 28);
        int n = nt * 8 + (lane >> 2);
        int k0 = ks * 16 + (lane & 3) * 2;
        __half h[4];
        #pragma unroll
        for (int ii = 0; ii < 2; ++ii)
            h[ii] = (n < WSQ) ? __float2half(attn_w[(n * 64 + k0 + ii) * WSQ + s]) : __half(0.f);
        #pragma unroll
        for (int ii = 0; ii < 2; ++ii)
            h[2 + ii] = (n < WSQ) ? __float2half(attn_w[(n * 64 + k0 + 8 + ii) * WSQ + s]) : __half(0.f);
        uint2 u;
        u.x = *(const uint32_t*)&h[0];
        u.y = *(const uint32_t*)&h[2];
        g_w2f[idx] = u;
        return;
    }
    int i = idx - WSQ * BTAPU2;
    if (i < NQKVF) {
        int lane = i & 31, r = i >> 5;
        int ks = r % 12, nt = r / 12;
        int oc = nt * 8 + (lane >> 2);
        int k  = ks * 8 + (lane & 3);
        uint2 u;
        u.x = tf32b(qkv_w[oc * 96 + k]);
        u.y = tf32b(qkv_w[oc * 96 + k + 4]);
        g_wqkv[i] = u;
        return;
    }
    i -= NQKVF;
    if (i < NPROJF) {
        int lane = i & 31, r = i >> 5;
        int ks = r % 12, nt = r / 12;
        int oc = nt * 8 + (lane >> 2);
        int k  = ks * 8 + (lane & 3);
        uint2 u;
        u.x = tf32b(proj_w[oc * 96 + k]);
        u.y = tf32b(proj_w[oc * 96 + k + 4]);
        g_wproj[i] = u;
    }
}

// ---------------- K1: 1x1 qkv conv via tf32 mma -----------------------------
__global__ __launch_bounds__(256, 2) void k1_qkv(const float* __restrict__ x,
                                                 const float* __restrict__ bias) {
    extern __shared__ float smem[];
    float* xs = smem;
    const int tid = threadIdx.x, lane = tid & 31, wid = tid >> 5;
    const int row = blockIdx.x, b = blockIdx.y;

    const float4* xb = (const float4*)(x + (((size_t)b * DIMC) << 14) + (row << 7));
    #pragma unroll
    for (int it = 0; it < 12; ++it) {
        int idx = tid + it * 256;
        int c = idx >> 5, p4 = idx & 31;
        float4 v = xb[(size_t)c * 4096 + p4];
        v.x = to_tf32(v.x); v.y = to_tf32(v.y); v.z = to_tf32(v.z); v.w = to_tf32(v.w);
        *(float4*)&xs[c * XPAD + p4 * 4] = v;
    }
    __syncthreads();

    const int pr = wid * 16 + (lane >> 2);
    uint32_t A[12][4];
    #pragma unroll
    for (int ks = 0; ks < 12; ++ks) {
        int k0 = ks * 8 + (lane & 3);
        A[ks][0] = __float_as_uint(xs[k0 * XPAD + pr]);
        A[ks][1] = __float_as_uint(xs[k0 * XPAD + pr + 8]);
        A[ks][2] = __float_as_uint(xs[(k0 + 4) * XPAD + pr]);
        A[ks][3] = __float_as_uint(xs[(k0 + 4) * XPAD + pr + 8]);
    }

    const int bh_base = b * HEADS;
    for (int nt = 0; nt < 36; ++nt) {
        uint2 bf[12];
        #pragma unroll
        for (int ks = 0; ks < 12; ++ks) bf[ks] = g_wqkv[(nt * 12 + ks) * 32 + lane];
        float acc[4] = {0.f, 0.f, 0.f, 0.f};
        #pragma unroll
        for (int ks = 0; ks < 12; ++ks) mma_tf32_16n8k8(acc, A[ks], bf[ks]);

        int oc = nt * 8 + ((lane & 3) << 1);
        float b0 = bias[oc], b1 = bias[oc + 1];
        if (nt < 24) {
            int oc96 = oc - (nt < 12 ? 0 : 96);
            int head = oc96 >> 5, ch = (oc96 & 31) + (nt < 12 ? 0 : 32);
            size_t base = ((((size_t)(bh_base + head) * 128 + row) << 7));
            float s = (nt < 12) ? QK_SCALE : 1.0f;
            #pragma unroll
            for (int i = 0; i < 2; ++i) {
                int px = pr + i * 8;
                __half2 h = __floats2half2_rn((acc[2 * i] + b0) * s, (acc[2 * i + 1] + b1) * s);
                *(__half2*)&g_qkh[(base + px) * 64 + ch] = h;
            }
        } else {
            int oc96 = oc - 192;
            int head = oc96 >> 5, ch = oc96 & 31;
            float* vb = g_v + ((((size_t)(bh_base + head) * 32) + ch) << 14) + (row << 7);
            #pragma unroll
            for (int i = 0; i < 2; ++i) {
                int px = pr + i * 8;
                vb[px]             = acc[2 * i] + b0;
                vb[(1 << 14) + px] = acc[2 * i + 1] + b1;
            }
        }
    }
}

// ---------------- K2: fp16 mma logits conv + softmax + attn.V --------------
// 8 warps; warp w owns mtiles {2w,2w+1} x all 7 ntiles.
// B fragments read straight from L1 (g_w2f, 88KB resident, shared by all
// warps/blocks on the SM). NO smem B stage, NO syncs in the 49-tap loop.
__global__ __launch_bounds__(256, 2) void k2_attn(const float* __restrict__ attn_b) {
    extern __shared__ char smemk2[];
    float* logits_sh = (float*)smemk2;
    float* v_sh = (float*)(smemk2 + 256 * 50 * 4);

    const int tid = threadIdx.x;
    const int lane = tid & 31, wid = tid >> 5;
    const int bh  = blockIdx.z;
    const int ty0 = blockIdx.y * 8;
    const int tx0 = blockIdx.x * 32;

    uint32_t sb;
    { uint64_t t_; asm("cvta.to.shared.u64 %0, %1;" : "=l"(t_) : "l"(smemk2)); sb = (uint32_t)t_; }

    // ---- load qk halo ----
    const uint4* qk4 = (const uint4*)g_qkh;
    for (int idx = tid; idx < HALO_PX * 8; idx += 256) {
        int pxi = idx >> 3, g = idx & 7;
        int hy = pxi / 38, hx = pxi - hy * 38;
        int gy = ty0 - 3 + hy, gx = tx0 - 3 + hx;
        uint4 val = make_uint4(0, 0, 0, 0);
        if ((unsigned)gy < 128u && (unsigned)gx < 128u)
            val = qk4[((((size_t)bh * 128 + gy) << 7) + gx) * 8 + g];
        *(uint4*)(smemk2 + pxi * PXB + g * 16) = val;
    }
    __syncthreads();

    // ldmatrix bases: warp w -> mtiles 2w, 2w+1
    uint32_t abase[2];
    #pragma unroll
    for (int m = 0; m < 2; ++m) {
        int p = (2 * wid + m) * 16 + (lane & 15);
        abase[m] = sb + ((p >> 5) * 38 + (p & 31)) * PXB + (lane >> 4) * 16;
    }

    float acc[2][7][4];
    #pragma unroll
    for (int m = 0; m < 2; ++m)
        #pragma unroll
        for (int nt = 0; nt < 7; ++nt)
            #pragma unroll
            for (int e = 0; e < 4; ++e) acc[m][nt][e] = 0.0f;

    const uint2* wbase = g_w2f + lane;
    #pragma unroll 1
    for (int s = 0; s < WSQ; ++s) {
        int dy = s / 7, dx = s - dy * 7;
        uint32_t toff = (uint32_t)(dy * 38 + dx) * PXB;
        const uint2* wtap = wbase + (size_t)s * BTAPU2;
        #pragma unroll
        for (int ks = 0; ks < 4; ++ks) {
            uint2 bf[7];
            #pragma unroll
            for (int nt = 0; nt < 7; ++nt) bf[nt] = __ldg(wtap + (ks * 7 + nt) * 32);
            uint32_t a[2][4];
            #pragma unroll
            for (int m = 0; m < 2; ++m) {
                asm volatile("ldmatrix.sync.aligned.m8n8.x4.shared.b16 {%0,%1,%2,%3}, [%4];"
                    : "=r"(a[m][0]), "=r"(a[m][1]), "=r"(a[m][2]), "=r"(a[m][3])
                    : "r"(abase[m] + toff + ks * 32));
            }
            #pragma unroll
            for (int nt = 0; nt < 7; ++nt) {
                mma_f16_16n8k16(acc[0][nt], a[0], bf[nt]);
                mma_f16_16n8k16(acc[1][nt], a[1], bf[nt]);
            }
        }
    }

    __syncthreads();   // halo reads done -> smem becomes logits buffer

    // ---- logits (+bias) to smem ----
    #pragma unroll
    for (int m = 0; m < 2; ++m) {
        int p0 = (2 * wid + m) * 16 + (lane >> 2);
        #pragma unroll
        for (int nt = 0; nt < 7; ++nt) {
            int t0 = nt * 8 + (lane & 3) * 2;
            if (t0 < WSQ) {
                float bb = attn_b[t0];
                logits_sh[p0 * 50 + t0]       = acc[m][nt][0] + bb;
                logits_sh[(p0 + 8) * 50 + t0] = acc[m][nt][2] + bb;
            }
            if (t0 + 1 < WSQ) {
                float bb = attn_b[t0 + 1];
                logits_sh[p0 * 50 + t0 + 1]       = acc[m][nt][1] + bb;
                logits_sh[(p0 + 8) * 50 + t0 + 1] = acc[m][nt][3] + bb;
            }
        }
    }
    __syncthreads();

    // ---- per-pixel softmax ----
    const int py = tid >> 5, px = tid & 31;
    float lg[WSQ];
    float mx = -1e30f;
    #pragma unroll
    for (int t = 0; t < WSQ; ++t) { lg[t] = logits_sh[tid * 50 + t]; mx = fmaxf(mx, lg[t]); }
    float sum = 0.0f;
    #pragma unroll
    for (int t = 0; t < WSQ; ++t) { lg[t] = __expf(lg[t] - mx); sum += lg[t]; }
    float inv = 1.0f / sum;
    #pragma unroll
    for (int t = 0; t < WSQ; ++t) lg[t] *= inv;

    const int b    = bh / HEADS;
    const int head = bh - b * HEADS;

    // ---- attn . V ----
    for (int vcblk = 0; vcblk < 4; ++vcblk) {
        __syncthreads();
        for (int idx = tid; idx < 8 * HALO_N; idx += 256) {
            int cc = idx / HALO_N;
            int rr = idx - cc * HALO_N;
            int hy = rr / 38, hx = rr - hy * 38;
            int gyy = ty0 - 3 + hy, gxx = tx0 - 3 + hx;
            float val = 0.0f;
            if ((unsigned)gyy < 128u && (unsigned)gxx < 128u)
                val = g_v[((((size_t)bh * 32) + vcblk * 8 + cc) << 14) + (gyy << 7) + gxx];
            v_sh[(hy * 40 + hx) * 8 + cc] = val;
        }
        __syncthreads();

        float o[8];
        #pragma unroll
        for (int vc = 0; vc < 8; ++vc) o[vc] = 0.0f;
        #pragma unroll
        for (int dy = 0; dy < 7; ++dy) {
            #pragma unroll
            for (int dx = 0; dx < 7; ++dx) {
                float a = lg[dy * 7 + dx];
                const float4* vp = (const float4*)&v_sh[((py + dy) * 40 + px + dx) * 8];
                float4 v0 = vp[0], v1 = vp[1];
                o[0] = fmaf(a, v0.x, o[0]); o[1] = fmaf(a, v0.y, o[1]);
                o[2] = fmaf(a, v0.z, o[2]); o[3] = fmaf(a, v0.w, o[3]);
                o[4] = fmaf(a, v1.x, o[4]); o[5] = fmaf(a, v1.y, o[5]);
                o[6] = fmaf(a, v1.z, o[6]); o[7] = fmaf(a, v1.w, o[7]);
            }
        }
        #pragma unroll
        for (int vc = 0; vc < 8; ++vc)
            g_att[((((size_t)b * DIMC) + head * 32 + vcblk * 8 + vc) << 14)
                  + ((ty0 + py) << 7) + (tx0 + px)] = o[vc];
    }
}

// ---------------- K3: 1x1 proj via tf32 mma -> d_out ------------------------
__global__ __launch_bounds__(256, 2) void k3_proj(const float* __restrict__ bias,
                                                  float* __restrict__ out) {
    extern __shared__ float smem[];
    float* xs = smem;
    const int tid = threadIdx.x, lane = tid & 31, wid = tid >> 5;
    const int row = blockIdx.x, b = blockIdx.y;

    const float4* xb = (const float4*)(g_att + (((size_t)b * DIMC) << 14) + (row << 7));
    #pragma unroll
    for (int it = 0; it < 12; ++it) {
        int idx = tid + it * 256;
        int c = idx >> 5, p4 = idx & 31;
        float4 v = xb[(size_t)c * 4096 + p4];
        v.x = to_tf32(v.x); v.y = to_tf32(v.y); v.z = to_tf32(v.z); v.w = to_tf32(v.w);
        *(float4*)&xs[c * XPAD + p4 * 4] = v;
    }
    __syncthreads();

    const int pr = wid * 16 + (lane >> 2);
    uint32_t A[12][4];
    #pragma unroll
    for (int ks = 0; ks < 12; ++ks) {
        int k0 = ks * 8 + (lane & 3);
        A[ks][0] = __float_as_uint(xs[k0 * XPAD + pr]);
        A[ks][1] = __float_as_uint(xs[k0 * XPAD + pr + 8]);
        A[ks][2] = __float_as_uint(xs[(k0 + 4) * XPAD + pr]);
        A[ks][3] = __float_as_uint(xs[(k0 + 4) * XPAD + pr + 8]);
    }

    for (int nt = 0; nt < 12; ++nt) {
        uint2 bf[12];
        #pragma unroll
        for (int ks = 0; ks < 12; ++ks) bf[ks] = g_wproj[(nt * 12 + ks) * 32 + lane];
        float acc[4] = {0.f, 0.f, 0.f, 0.f};
        #pragma unroll
        for (int ks = 0; ks < 12; ++ks) mma_tf32_16n8k8(acc, A[ks], bf[ks]);

        int oc = nt * 8 + ((lane & 3) << 1);
        float b0 = bias[oc], b1 = bias[oc + 1];
        float* ob = out + ((((size_t)b * DIMC) + oc) << 14) + (row << 7);
        #pragma unroll
        for (int i = 0; i < 2; ++i) {
            int px = pr + i * 8;
            ob[px]             = acc[2 * i] + b0;
            ob[(1 << 14) + px] = acc[2 * i + 1] + b1;
        }
    }
}

// ---------------- launch ---------------------------------------------------
extern "C" void kernel_launch(void* const* d_in, const int* in_sizes, int n_in,
                              void* d_out, int out_size) {
    const float* x      = (const float*)d_in[0];
    const float* qkv_w  = (const float*)d_in[1];
    const float* qkv_b  = (const float*)d_in[2];
    const float* attn_w = (const float*)d_in[3];
    const float* attn_b = (const float*)d_in[4];
    const float* proj_w = (const float*)d_in[5];
    const float* proj_b = (const float*)d_in[6];
    float* out = (float*)d_out;

    cudaFuncSetAttribute(k1_qkv,  cudaFuncAttributeMaxDynamicSharedMemorySize, SMEM_G);
    cudaFuncSetAttribute(k2_attn, cudaFuncAttributeMaxDynamicSharedMemorySize, SMEM_K2);
    cudaFuncSetAttribute(k3_proj, cudaFuncAttributeMaxDynamicSharedMemorySize, SMEM_G);

    const int k0n = WSQ * BTAPU2 + NQKVF + NPROJF;
    k0_prep<<<(k0n + 255) / 256, 256>>>(attn_w, qkv_w, proj_w);
    k1_qkv<<<dim3(128, BATCH), 256, SMEM_G>>>(x, qkv_b);
    k2_attn<<<dim3(4, 16, NBH), 256, SMEM_K2>>>(attn_b);
    k3_proj<<<dim3(128, BATCH), 256, SMEM_G>>>(proj_b, out);
}